// round 4
// baseline (speedup 1.0000x reference)
#include <cuda_runtime.h>
#include <math.h>

#define NB 4
#define NT 1024
#define ND 1024
#define NH 16
#define NL 2
#define NE 8
#define NDFF 4096
#define NV 50257
#define NHD 64
#define NTOK 4096   // NB*NT
#define NTOPK 1024  // CAP*NB*NT/NE

// ---------------- scratch (static device allocations; no cudaMalloc) ----------
__device__ float g_x[NTOK * ND];
__device__ float g_xn[NTOK * ND];
__device__ float g_qkv[NTOK * 3 * ND];
__device__ float g_S[(size_t)NB * NH * NT * NT];       // 268 MB attention scores
__device__ float g_att[NTOK * ND];
__device__ float g_h[(size_t)NE * NTOPK * NDFF];       // 134 MB MoE hidden
__device__ float g_probs[NTOK * NE];
__device__ float g_wsel[NE * NTOPK];
__device__ int   g_sel[NE * NTOPK];
__device__ float g_xf[NB * ND];

// ---------------- embedding ---------------------------------------------------
__global__ void embed_kernel(const int* __restrict__ idx, const float* __restrict__ wte,
                             const float* __restrict__ wpe, float* __restrict__ x) {
    int n = blockIdx.x;
    int t = n & (NT - 1);
    long long r = idx[n];
    const float* a = wte + r * ND;
    const float* b = wpe + (long long)t * ND;
    float* o = x + (long long)n * ND;
    for (int d = threadIdx.x; d < ND; d += blockDim.x) o[d] = a[d] + b[d];
}

// ---------------- rmsnorm -----------------------------------------------------
// input row = blockIdx.x*rowMul + rowAdd ; output row = blockIdx.x
__global__ void rmsnorm_kernel(const float* __restrict__ x, const float* __restrict__ w,
                               float* __restrict__ out, int rowMul, int rowAdd) {
    int orow = blockIdx.x;
    long long irow = (long long)orow * rowMul + rowAdd;
    const float* xr = x + irow * ND;
    __shared__ float red[256];
    float s = 0.f;
    for (int d = threadIdx.x; d < ND; d += 256) { float v = xr[d]; s += v * v; }
    red[threadIdx.x] = s; __syncthreads();
    for (int o = 128; o > 0; o >>= 1) {
        if (threadIdx.x < o) red[threadIdx.x] += red[threadIdx.x + o];
        __syncthreads();
    }
    float scale = 1.0f / sqrtf(red[0] * (1.0f / ND) + 1e-6f);
    float* o = out + (long long)orow * ND;
    for (int d = threadIdx.x; d < ND; d += 256) o[d] = xr[d] * scale * w[d];
}

// ---------------- generic batched SGEMM (NT or NN) ---------------------------
// C[m,n] = alpha * sum_k A[m,k] * B', B' = B[n,k] (transB=0) or B[k,n] (transB=1)
// batch z: z1 = z/zdiv, z2 = z%zdiv applied to A/B/C base pointers.
// rowsA: optional gather of A rows (index rowsA[z*M + m]).
// epilogue: 0 = store (+optional residual), 1 = exact GELU store,
//           2 = atomicAdd(scatter[rowsOut[z*M+m]*ldc + n], rowScale[z*M+m]*acc)
#define BM 128
#define BN 128
#define BKK 16

__global__ __launch_bounds__(256) void gemm_kernel(
    const float* __restrict__ A, const float* __restrict__ B, float* __restrict__ C,
    int M, int N, int K, int lda, int ldb, int ldc,
    long long sA1, long long sA2, long long sB1, long long sB2,
    long long sC1, long long sC2, int zdiv, float alpha,
    const float* __restrict__ residual, const int* __restrict__ rowsA,
    int transB, int epilogue,
    const int* __restrict__ rowsOut, const float* __restrict__ rowScale,
    float* __restrict__ scatter)
{
    __shared__ float As[BKK][BM];
    __shared__ float Bs[BKK][BN];

    int z = blockIdx.z;
    int z1 = z / zdiv, z2 = z - z1 * zdiv;
    A += z1 * sA1 + z2 * sA2;
    B += z1 * sB1 + z2 * sB2;
    if (C) C += z1 * sC1 + z2 * sC2;

    int m0 = blockIdx.y * BM, n0 = blockIdx.x * BN;
    int tid = threadIdx.x;
    int tx = tid & 15, ty = tid >> 4;

    float acc[8][8];
#pragma unroll
    for (int i = 0; i < 8; i++)
#pragma unroll
        for (int j = 0; j < 8; j++) acc[i][j] = 0.f;

    // A loader mapping (A always [rows, K] row-major, K contiguous)
    int am = tid >> 1, ak = (tid & 1) * 8;
    int gm = m0 + am;
    bool amOk = gm < M;
    long long arow = gm;
    if (rowsA && amOk) arow = rowsA[(long long)z * M + gm];
    const float* aBase = A + arow * (long long)lda;   // FIX: no +ak here (ak is in kk)

    for (int k0 = 0; k0 < K; k0 += BKK) {
#pragma unroll
        for (int j = 0; j < 8; j++) {
            int kk = ak + j;
            float v = 0.f;
            if (amOk && (k0 + kk) < K) v = aBase[k0 + kk];
            As[kk][am] = v;
        }
        if (!transB) {
            int bn = tid >> 1, bk = (tid & 1) * 8;
            int gn = n0 + bn;
            bool ok = gn < N;
            const float* bp = B + (long long)gn * ldb + k0 + bk;
#pragma unroll
            for (int j = 0; j < 8; j++) {
                float v = 0.f;
                if (ok && (k0 + bk + j) < K) v = bp[j];
                Bs[bk + j][bn] = v;
            }
        } else {
            int bk = tid >> 4, bn = (tid & 15) * 8;
            int gk = k0 + bk;
            bool ok = gk < K;
            const float* bp = B + (long long)gk * ldb + n0 + bn;
#pragma unroll
            for (int j = 0; j < 8; j++) {
                float v = 0.f;
                if (ok && (n0 + bn + j) < N) v = bp[j];
                Bs[bk][bn + j] = v;
            }
        }
        __syncthreads();
#pragma unroll
        for (int kk = 0; kk < BKK; kk++) {
            float4 a0 = *(const float4*)&As[kk][ty * 8];
            float4 a1 = *(const float4*)&As[kk][ty * 8 + 4];
            float4 b0 = *(const float4*)&Bs[kk][tx * 8];
            float4 b1 = *(const float4*)&Bs[kk][tx * 8 + 4];
            float a[8] = {a0.x, a0.y, a0.z, a0.w, a1.x, a1.y, a1.z, a1.w};
            float b[8] = {b0.x, b0.y, b0.z, b0.w, b1.x, b1.y, b1.z, b1.w};
#pragma unroll
            for (int i = 0; i < 8; i++)
#pragma unroll
                for (int j = 0; j < 8; j++) acc[i][j] += a[i] * b[j];
        }
        __syncthreads();
    }

#pragma unroll
    for (int i = 0; i < 8; i++) {
        int m = m0 + ty * 8 + i;
        if (m >= M) continue;
#pragma unroll
        for (int j = 0; j < 8; j++) {
            int n = n0 + tx * 8 + j;
            if (n >= N) continue;
            float v = acc[i][j] * alpha;
            if (epilogue == 0) {
                if (residual) v += residual[(long long)m * ldc + n];
                C[(long long)m * ldc + n] = v;
            } else if (epilogue == 1) {
                C[(long long)m * ldc + n] =
                    0.5f * v * (1.0f + erff(v * 0.70710678118654752440f));
            } else {
                long long r = rowsOut[(long long)z * M + m];
                float wsc = rowScale[(long long)z * M + m];
                atomicAdd(&scatter[r * ldc + n], wsc * v);
            }
        }
    }
}

// ---------------- causal softmax on score rows -------------------------------
__global__ void softmax_kernel(float* __restrict__ S) {
    int q = blockIdx.x;
    long long z = blockIdx.y;
    float* row = S + z * (long long)NT * NT + (long long)q * NT;
    int len = q + 1;
    __shared__ float red[128];
    int tid = threadIdx.x;
    float mx = -1e30f;
    for (int i = tid; i < len; i += 128) mx = fmaxf(mx, row[i]);
    red[tid] = mx; __syncthreads();
    for (int o = 64; o > 0; o >>= 1) {
        if (tid < o) red[tid] = fmaxf(red[tid], red[tid + o]);
        __syncthreads();
    }
    mx = red[0]; __syncthreads();
    float s = 0.f;
    for (int i = tid; i < len; i += 128) { float e = expf(row[i] - mx); row[i] = e; s += e; }
    red[tid] = s; __syncthreads();
    for (int o = 64; o > 0; o >>= 1) {
        if (tid < o) red[tid] += red[tid + o];
        __syncthreads();
    }
    float inv = 1.0f / red[0];
    for (int i = tid; i < len; i += 128) row[i] *= inv;
    for (int i = len + tid; i < NT; i += 128) row[i] = 0.f;  // zero masked region for PV gemm
}

// ---------------- router logits + softmax over experts -----------------------
__global__ void router_kernel(const float* __restrict__ xn, const float* __restrict__ wr,
                              float* __restrict__ probs) {
    int n = blockIdx.x;
    const float* xr = xn + (long long)n * ND;
    float acc[NE];
#pragma unroll
    for (int e = 0; e < NE; e++) acc[e] = 0.f;
    for (int d = threadIdx.x; d < ND; d += 128) {
        float xv = xr[d];
#pragma unroll
        for (int e = 0; e < NE; e++) acc[e] += xv * wr[e * ND + d];
    }
    __shared__ float red[128];
    __shared__ float logit[NE];
    for (int e = 0; e < NE; e++) {
        red[threadIdx.x] = acc[e]; __syncthreads();
        for (int o = 64; o > 0; o >>= 1) {
            if (threadIdx.x < o) red[threadIdx.x] += red[threadIdx.x + o];
            __syncthreads();
        }
        if (threadIdx.x == 0) logit[e] = red[0];
        __syncthreads();
    }
    if (threadIdx.x == 0) {
        float mx = logit[0];
        for (int e = 1; e < NE; e++) mx = fmaxf(mx, logit[e]);
        float s = 0.f; float ex[NE];
        for (int e = 0; e < NE; e++) { ex[e] = expf(logit[e] - mx); s += ex[e]; }
        float inv = 1.0f / s;
        for (int e = 0; e < NE; e++) probs[(long long)n * NE + e] = ex[e] * inv;
    }
}

// ---------------- per-expert top-k via in-smem bitonic sort -------------------
// key: (value desc, index asc) -> matches jax.lax.top_k tie-breaking
__global__ void topk_kernel(const float* __restrict__ probs, int* __restrict__ sel,
                            float* __restrict__ weights) {
    int e = blockIdx.x;
    __shared__ float v[NTOK];
    __shared__ int ix[NTOK];
    int tid = threadIdx.x;
    for (int i = tid; i < NTOK; i += 1024) { v[i] = probs[(long long)i * NE + e]; ix[i] = i; }
    __syncthreads();
    for (int k = 2; k <= NTOK; k <<= 1) {
        for (int j = k >> 1; j > 0; j >>= 1) {
            for (int i = tid; i < NTOK; i += 1024) {
                int p = i ^ j;
                if (p > i) {
                    float va = v[i], vb = v[p];
                    int ia = ix[i], ib = ix[p];
                    bool sw;
                    if ((i & k) == 0) sw = (vb > va) || (vb == va && ib < ia);
                    else              sw = (va > vb) || (va == vb && ia < ib);
                    if (sw) { v[i] = vb; v[p] = va; ix[i] = ib; ix[p] = ia; }
                }
            }
            __syncthreads();
        }
    }
    for (int i = tid; i < NTOPK; i += 1024) {
        sel[e * NTOPK + i] = ix[i];
        weights[e * NTOPK + i] = v[i];
    }
}

// ---------------- LM head: logits for last token of each batch ----------------
__global__ void lmhead_kernel(const float* __restrict__ xf, const float* __restrict__ wte,
                              float* __restrict__ out) {
    __shared__ float xs[NB * ND];
    for (int i = threadIdx.x; i < NB * ND; i += 256) xs[i] = xf[i];
    __syncthreads();
    int warp = threadIdx.x >> 5, lane = threadIdx.x & 31;
    int vtok = blockIdx.x * 8 + warp;
    if (vtok < NV) {
        const float* wrow = wte + (long long)vtok * ND;
        float a0 = 0.f, a1 = 0.f, a2 = 0.f, a3 = 0.f;
        for (int d = lane; d < ND; d += 32) {
            float w = wrow[d];
            a0 += w * xs[d];
            a1 += w * xs[ND + d];
            a2 += w * xs[2 * ND + d];
            a3 += w * xs[3 * ND + d];
        }
#pragma unroll
        for (int o = 16; o > 0; o >>= 1) {
            a0 += __shfl_down_sync(0xffffffffu, a0, o);
            a1 += __shfl_down_sync(0xffffffffu, a1, o);
            a2 += __shfl_down_sync(0xffffffffu, a2, o);
            a3 += __shfl_down_sync(0xffffffffu, a3, o);
        }
        if (lane == 0) {
            out[0 * NV + vtok] = a0;
            out[1 * NV + vtok] = a1;
            out[2 * NV + vtok] = a2;
            out[3 * NV + vtok] = a3;
        }
    }
}

// ---------------- host-side orchestration ------------------------------------
extern "C" void kernel_launch(void* const* d_in, const int* in_sizes, int n_in,
                              void* d_out, int out_size) {
    (void)in_sizes; (void)n_in; (void)out_size;
    const int*   idx         = (const int*)d_in[0];
    const float* wte         = (const float*)d_in[1];
    const float* wpe         = (const float*)d_in[2];
    const float* ln1_w       = (const float*)d_in[3];
    const float* attn_w      = (const float*)d_in[4];
    const float* attn_proj_w = (const float*)d_in[5];
    const float* ln2_w       = (const float*)d_in[6];
    const float* router_w    = (const float*)d_in[7];
    const float* fc_w        = (const float*)d_in[8];
    const float* proj_w      = (const float*)d_in[9];
    const float* lnf_w       = (const float*)d_in[10];
    float* out = (float*)d_out;

    void *p0, *p1, *p2, *p3, *p4, *p5, *p6, *p7, *p8, *p9;
    cudaGetSymbolAddress(&p0, g_x);
    cudaGetSymbolAddress(&p1, g_xn);
    cudaGetSymbolAddress(&p2, g_qkv);
    cudaGetSymbolAddress(&p3, g_S);
    cudaGetSymbolAddress(&p4, g_att);
    cudaGetSymbolAddress(&p5, g_h);
    cudaGetSymbolAddress(&p6, g_probs);
    cudaGetSymbolAddress(&p7, g_wsel);
    cudaGetSymbolAddress(&p8, g_sel);
    cudaGetSymbolAddress(&p9, g_xf);
    float* x     = (float*)p0;
    float* xn    = (float*)p1;
    float* qkv   = (float*)p2;
    float* S     = (float*)p3;
    float* att   = (float*)p4;
    float* h     = (float*)p5;
    float* probs = (float*)p6;
    float* wsel  = (float*)p7;
    int*   sel   = (int*)p8;
    float* xf    = (float*)p9;

    embed_kernel<<<NTOK, 256>>>(idx, wte, wpe, x);

    for (int l = 0; l < NL; l++) {
        const float* ln1 = ln1_w + l * ND;
        const float* aw  = attn_w + (long long)l * 3 * ND * ND;
        const float* apw = attn_proj_w + (long long)l * ND * ND;
        const float* ln2 = ln2_w + l * ND;
        const float* rw  = router_w + (long long)l * NE * ND;
        const float* fw  = fc_w + (long long)l * NE * NDFF * ND;
        const float* pjw = proj_w + (long long)l * NE * ND * NDFF;

        // ---- attention block ----
        rmsnorm_kernel<<<NTOK, 256>>>(x, ln1, xn, 1, 0);
        // qkv = xn @ attn_w^T : [4096, 3072]
        gemm_kernel<<<dim3(3 * ND / BN, NTOK / BM, 1), 256>>>(
            xn, aw, qkv, NTOK, 3 * ND, ND, ND, ND, 3 * ND,
            0, 0, 0, 0, 0, 0, 1, 1.0f,
            nullptr, nullptr, 0, 0, nullptr, nullptr, nullptr);
        // S = (Q K^T)/8 per (b,h)
        gemm_kernel<<<dim3(NT / BN, NT / BM, NB * NH), 256>>>(
            qkv, qkv + ND, S, NT, NT, NHD, 3 * ND, 3 * ND, NT,
            (long long)NT * 3 * ND, NHD, (long long)NT * 3 * ND, NHD,
            (long long)NH * NT * NT, (long long)NT * NT, NH, 0.125f,
            nullptr, nullptr, 0, 0, nullptr, nullptr, nullptr);
        softmax_kernel<<<dim3(NT, NB * NH), 128>>>(S);
        // att = P V per (b,h)   (V is K-major -> transB=1)
        gemm_kernel<<<dim3(1, NT / BM, NB * NH), 256>>>(
            S, qkv + 2 * ND, att, NT, NHD, NT, NT, 3 * ND, ND,
            (long long)NH * NT * NT, (long long)NT * NT,
            (long long)NT * 3 * ND, NHD,
            (long long)NT * ND, NHD, NH, 1.0f,
            nullptr, nullptr, 1, 0, nullptr, nullptr, nullptr);
        // x = x + att @ attn_proj^T
        gemm_kernel<<<dim3(ND / BN, NTOK / BM, 1), 256>>>(
            att, apw, x, NTOK, ND, ND, ND, ND, ND,
            0, 0, 0, 0, 0, 0, 1, 1.0f,
            x, nullptr, 0, 0, nullptr, nullptr, nullptr);

        // ---- MoE block ----
        rmsnorm_kernel<<<NTOK, 256>>>(x, ln2, xn, 1, 0);
        router_kernel<<<NTOK, 128>>>(xn, rw, probs);
        topk_kernel<<<NE, 1024>>>(probs, sel, wsel);
        // h[e] = gelu( xn[sel[e]] @ fc_w[e]^T ) : [1024, 4096] per expert
        gemm_kernel<<<dim3(NDFF / BN, NTOPK / BM, NE), 256>>>(
            xn, fw, h, NTOPK, NDFF, ND, ND, ND, NDFF,
            0, 0, (long long)NDFF * ND, 0, (long long)NTOPK * NDFF, 0, 1, 1.0f,
            nullptr, sel, 0, 1, nullptr, nullptr, nullptr);
        // x[sel[e,k]] += w[e,k] * (h[e] @ proj_w[e]^T)
        gemm_kernel<<<dim3(ND / BN, NTOPK / BM, NE), 256>>>(
            h, pjw, nullptr, NTOPK, ND, NDFF, NDFF, NDFF, ND,
            (long long)NTOPK * NDFF, 0, (long long)ND * NDFF, 0, 0, 0, 1, 1.0f,
            nullptr, nullptr, 0, 2, sel, wsel, x);
    }

    // final rmsnorm only on the 4 last-position rows, then tied LM head
    rmsnorm_kernel<<<NB, 256>>>(x, lnf_w, xf, NT, NT - 1);
    lmhead_kernel<<<(NV + 7) / 8, 256>>>(xf, wte, out);
}

// round 7
// speedup vs baseline: 1.1530x; 1.1530x over previous
#include <cuda_runtime.h>
#include <cuda_bf16.h>
#include <math.h>
#include <stdint.h>

#define NB 4
#define NT 1024
#define ND 1024
#define NH 16
#define NL 2
#define NE 8
#define NDFF 4096
#define NV 50257
#define NHD 64
#define NTOK 4096   // NB*NT
#define NTOPK 1024  // CAP*NB*NT/NE

// ---------------- scratch (static device allocations; no cudaMalloc) ----------
__device__ float g_x[NTOK * ND];
__device__ float g_xn[NTOK * ND];
__device__ float g_qkv[NTOK * 3 * ND];
__device__ float g_S[(size_t)NB * NH * NT * NT];       // 268 MB attention scores
__device__ float g_att[NTOK * ND];
__device__ float g_h[(size_t)NE * NTOPK * NDFF];       // 134 MB MoE hidden
__device__ float g_probs[NTOK * NE];
__device__ float g_wsel[NE * NTOPK];
__device__ int   g_sel[NE * NTOPK];
__device__ float g_xf[NB * ND];

// ---------------- embedding ---------------------------------------------------
__global__ void embed_kernel(const int* __restrict__ idx, const float* __restrict__ wte,
                             const float* __restrict__ wpe, float* __restrict__ x) {
    int n = blockIdx.x;
    int t = n & (NT - 1);
    long long r = idx[n];
    const float* a = wte + r * ND;
    const float* b = wpe + (long long)t * ND;
    float* o = x + (long long)n * ND;
    for (int d = threadIdx.x; d < ND; d += blockDim.x) o[d] = a[d] + b[d];
}

// ---------------- rmsnorm -----------------------------------------------------
__global__ void rmsnorm_kernel(const float* __restrict__ x, const float* __restrict__ w,
                               float* __restrict__ out, int rowMul, int rowAdd) {
    int orow = blockIdx.x;
    long long irow = (long long)orow * rowMul + rowAdd;
    const float* xr = x + irow * ND;
    __shared__ float red[256];
    float s = 0.f;
    for (int d = threadIdx.x; d < ND; d += 256) { float v = xr[d]; s += v * v; }
    red[threadIdx.x] = s; __syncthreads();
    for (int o = 128; o > 0; o >>= 1) {
        if (threadIdx.x < o) red[threadIdx.x] += red[threadIdx.x + o];
        __syncthreads();
    }
    float scale = 1.0f / sqrtf(red[0] * (1.0f / ND) + 1e-6f);
    float* o = out + (long long)orow * ND;
    for (int d = threadIdx.x; d < ND; d += 256) o[d] = xr[d] * scale * w[d];
}

// ---------------- tensor-core batched GEMM (split-bf16, fp32-accurate) --------
// C[m,n] = alpha * sum_k A[m,k] * B', B' = B[n,k] (transB=0) or B[k,n] (transB=1)
// Each fp32 operand is split hi/lo bf16; product = Ah*Bh + Ah*Bl + Al*Bh via
// mma.sync.m16n8k16 (fp32 accum). Error ~3e-5 per GEMM.
#define BM 128
#define BN 128
#define BK 32
#define LDS_PAD 36   // BK + 4 bf16 pad: conflict-free fragment loads

__device__ __forceinline__ void mma_bf16(float* c, const uint32_t* a,
                                         uint32_t b0, uint32_t b1) {
    asm volatile(
        "mma.sync.aligned.m16n8k16.row.col.f32.bf16.bf16.f32 "
        "{%0,%1,%2,%3}, {%4,%5,%6,%7}, {%8,%9}, {%0,%1,%2,%3};"
        : "+f"(c[0]), "+f"(c[1]), "+f"(c[2]), "+f"(c[3])
        : "r"(a[0]), "r"(a[1]), "r"(a[2]), "r"(a[3]), "r"(b0), "r"(b1));
}

__device__ __forceinline__ void split_store(float v, __nv_bfloat16* ph, __nv_bfloat16* pl) {
    __nv_bfloat16 h = __float2bfloat16(v);
    *ph = h;
    *pl = __float2bfloat16(v - __bfloat162float(h));
}

__device__ __forceinline__ uint32_t ldb32(const __nv_bfloat16* p) {
    return *(const uint32_t*)p;
}

__global__ __launch_bounds__(256) void gemm_kernel(
    const float* __restrict__ A, const float* __restrict__ B, float* __restrict__ C,
    int M, int N, int K, int lda, int ldb, int ldc,
    long long sA1, long long sA2, long long sB1, long long sB2,
    long long sC1, long long sC2, int zdiv, float alpha,
    const float* __restrict__ residual, const int* __restrict__ rowsA,
    int transB, int epilogue,
    const int* __restrict__ rowsOut, const float* __restrict__ rowScale,
    float* __restrict__ scatter)
{
    __shared__ __nv_bfloat16 AsH[BM][LDS_PAD];
    __shared__ __nv_bfloat16 AsL[BM][LDS_PAD];
    __shared__ __nv_bfloat16 BsH[BN][LDS_PAD];
    __shared__ __nv_bfloat16 BsL[BN][LDS_PAD];

    int z = blockIdx.z;
    int z1 = z / zdiv, z2 = z - z1 * zdiv;
    A += z1 * sA1 + z2 * sA2;
    B += z1 * sB1 + z2 * sB2;
    if (C) C += z1 * sC1 + z2 * sC2;

    int m0 = blockIdx.y * BM, n0 = blockIdx.x * BN;
    int tid = threadIdx.x;
    int lane = tid & 31;
    int warpId = tid >> 5;
    int wm = (warpId & 3) * 32;   // warp m-offset within block tile
    int wn = (warpId >> 2) * 64;  // warp n-offset within block tile
    int fr = lane >> 2;           // fragment row 0..7
    int fc = (lane & 3) * 2;      // fragment col pair base

    float acc[2][8][4];
#pragma unroll
    for (int mi = 0; mi < 2; mi++)
#pragma unroll
        for (int ni = 0; ni < 8; ni++)
#pragma unroll
            for (int t = 0; t < 4; t++) acc[mi][ni][t] = 0.f;

    // A loader mapping (A always [rows, K] row-major, K contiguous)
    int am = tid >> 1, ak = (tid & 1) * 16;
    int gm = m0 + am;
    bool amOk = gm < M;
    long long arow = gm;
    if (rowsA && amOk) arow = rowsA[(long long)z * M + gm];
    const float* aBase = A + arow * (long long)lda;

    for (int k0 = 0; k0 < K; k0 += BK) {
        // ---- load + split A tile ----
#pragma unroll
        for (int j = 0; j < 16; j++) {
            int kk = ak + j;
            float v = 0.f;
            if (amOk && (k0 + kk) < K) v = aBase[k0 + kk];
            split_store(v, &AsH[am][kk], &AsL[am][kk]);
        }
        // ---- load + split B tile ----
        if (!transB) {
            int bn = tid >> 1, bk = (tid & 1) * 16;
            int gn = n0 + bn;
            bool ok = gn < N;
            const float* bp = B + (long long)gn * ldb + k0;
#pragma unroll
            for (int j = 0; j < 16; j++) {
                int kk = bk + j;
                float v = 0.f;
                if (ok && (k0 + kk) < K) v = bp[kk];
                split_store(v, &BsH[bn][kk], &BsL[bn][kk]);
            }
        } else {
            int bk = tid >> 3, bn8 = (tid & 7) * 16;
            int gk = k0 + bk;
            bool ok = gk < K;
            const float* bp = B + (long long)gk * ldb + n0 + bn8;
#pragma unroll
            for (int j = 0; j < 16; j++) {
                float v = 0.f;
                if (ok && (n0 + bn8 + j) < N) v = bp[j];
                split_store(v, &BsH[bn8 + j][bk], &BsL[bn8 + j][bk]);
            }
        }
        __syncthreads();

        // ---- tensor-core inner product: 2 k16 steps ----
#pragma unroll
        for (int ks = 0; ks < 2; ks++) {
            int kk = ks * 16;
            uint32_t ah[2][4], al[2][4];
#pragma unroll
            for (int mi = 0; mi < 2; mi++) {
                int r0 = wm + mi * 16 + fr;
                ah[mi][0] = ldb32(&AsH[r0][kk + fc]);
                ah[mi][1] = ldb32(&AsH[r0 + 8][kk + fc]);
                ah[mi][2] = ldb32(&AsH[r0][kk + 8 + fc]);
                ah[mi][3] = ldb32(&AsH[r0 + 8][kk + 8 + fc]);
                al[mi][0] = ldb32(&AsL[r0][kk + fc]);
                al[mi][1] = ldb32(&AsL[r0 + 8][kk + fc]);
                al[mi][2] = ldb32(&AsL[r0][kk + 8 + fc]);
                al[mi][3] = ldb32(&AsL[r0 + 8][kk + 8 + fc]);
            }
#pragma unroll
            for (int ni = 0; ni < 8; ni++) {
                int col = wn + ni * 8 + fr;
                uint32_t bh0 = ldb32(&BsH[col][kk + fc]);
                uint32_t bh1 = ldb32(&BsH[col][kk + 8 + fc]);
                uint32_t bl0 = ldb32(&BsL[col][kk + fc]);
                uint32_t bl1 = ldb32(&BsL[col][kk + 8 + fc]);
#pragma unroll
                for (int mi = 0; mi < 2; mi++) {
                    mma_bf16(acc[mi][ni], ah[mi], bh0, bh1);  // hi*hi
                    mma_bf16(acc[mi][ni], ah[mi], bl0, bl1);  // hi*lo
                    mma_bf16(acc[mi][ni], al[mi], bh0, bh1);  // lo*hi
                }
            }
        }
        __syncthreads();
    }

    // ---- epilogue ----
#pragma unroll
    for (int mi = 0; mi < 2; mi++) {
#pragma unroll
        for (int ni = 0; ni < 8; ni++) {
            int mBase = m0 + wm + mi * 16 + fr;
            int nBase = n0 + wn + ni * 8 + fc;
#pragma unroll
            for (int half = 0; half < 2; half++) {
                int m = mBase + half * 8;
                if (m >= M) continue;
#pragma unroll
                for (int t = 0; t < 2; t++) {
                    int n = nBase + t;
                    if (n >= N) continue;
                    float v = acc[mi][ni][half * 2 + t] * alpha;
                    if (epilogue == 0) {
                        if (residual) v += residual[(long long)m * ldc + n];
                        C[(long long)m * ldc + n] = v;
                    } else if (epilogue == 1) {
                        C[(long long)m * ldc + n] =
                            0.5f * v * (1.0f + erff(v * 0.70710678118654752440f));
                    } else {
                        long long rr = rowsOut[(long long)z * M + m];
                        float wsc = rowScale[(long long)z * M + m];
                        atomicAdd(&scatter[rr * ldc + n], wsc * v);
                    }
                }
            }
        }
    }
}

// ---------------- causal softmax on score rows -------------------------------
__global__ void softmax_kernel(float* __restrict__ S) {
    int q = blockIdx.x;
    long long z = blockIdx.y;
    float* row = S + z * (long long)NT * NT + (long long)q * NT;
    int len = q + 1;
    __shared__ float red[128];
    int tid = threadIdx.x;
    float mx = -1e30f;
    for (int i = tid; i < len; i += 128) mx = fmaxf(mx, row[i]);
    red[tid] = mx; __syncthreads();
    for (int o = 64; o > 0; o >>= 1) {
        if (tid < o) red[tid] = fmaxf(red[tid], red[tid + o]);
        __syncthreads();
    }
    mx = red[0]; __syncthreads();
    float s = 0.f;
    for (int i = tid; i < len; i += 128) { float e = expf(row[i] - mx); row[i] = e; s += e; }
    red[tid] = s; __syncthreads();
    for (int o = 64; o > 0; o >>= 1) {
        if (tid < o) red[tid] += red[tid + o];
        __syncthreads();
    }
    float inv = 1.0f / red[0];
    for (int i = tid; i < len; i += 128) row[i] *= inv;
    for (int i = len + tid; i < NT; i += 128) row[i] = 0.f;  // zero masked region for PV gemm
}

// ---------------- router logits + softmax over experts -----------------------
__global__ void router_kernel(const float* __restrict__ xn, const float* __restrict__ wr,
                              float* __restrict__ probs) {
    int n = blockIdx.x;
    const float* xr = xn + (long long)n * ND;
    float acc[NE];
#pragma unroll
    for (int e = 0; e < NE; e++) acc[e] = 0.f;
    for (int d = threadIdx.x; d < ND; d += 128) {
        float xv = xr[d];
#pragma unroll
        for (int e = 0; e < NE; e++) acc[e] += xv * wr[e * ND + d];
    }
    __shared__ float red[128];
    __shared__ float logit[NE];
    for (int e = 0; e < NE; e++) {
        red[threadIdx.x] = acc[e]; __syncthreads();
        for (int o = 64; o > 0; o >>= 1) {
            if (threadIdx.x < o) red[threadIdx.x] += red[threadIdx.x + o];
            __syncthreads();
        }
        if (threadIdx.x == 0) logit[e] = red[0];
        __syncthreads();
    }
    if (threadIdx.x == 0) {
        float mx = logit[0];
        for (int e = 1; e < NE; e++) mx = fmaxf(mx, logit[e]);
        float s = 0.f; float ex[NE];
        for (int e = 0; e < NE; e++) { ex[e] = expf(logit[e] - mx); s += ex[e]; }
        float inv = 1.0f / s;
        for (int e = 0; e < NE; e++) probs[(long long)n * NE + e] = ex[e] * inv;
    }
}

// ---------------- per-expert top-k via in-smem bitonic sort -------------------
__global__ void topk_kernel(const float* __restrict__ probs, int* __restrict__ sel,
                            float* __restrict__ weights) {
    int e = blockIdx.x;
    __shared__ float v[NTOK];
    __shared__ int ix[NTOK];
    int tid = threadIdx.x;
    for (int i = tid; i < NTOK; i += 1024) { v[i] = probs[(long long)i * NE + e]; ix[i] = i; }
    __syncthreads();
    for (int k = 2; k <= NTOK; k <<= 1) {
        for (int j = k >> 1; j > 0; j >>= 1) {
            for (int i = tid; i < NTOK; i += 1024) {
                int p = i ^ j;
                if (p > i) {
                    float va = v[i], vb = v[p];
                    int ia = ix[i], ib = ix[p];
                    bool sw;
                    if ((i & k) == 0) sw = (vb > va) || (vb == va && ib < ia);
                    else              sw = (va > vb) || (va == vb && ia < ib);
                    if (sw) { v[i] = vb; v[p] = va; ix[i] = ib; ix[p] = ia; }
                }
            }
            __syncthreads();
        }
    }
    for (int i = tid; i < NTOPK; i += 1024) {
        sel[e * NTOPK + i] = ix[i];
        weights[e * NTOPK + i] = v[i];
    }
}

// ---------------- LM head: logits for last token of each batch ----------------
__global__ void lmhead_kernel(const float* __restrict__ xf, const float* __restrict__ wte,
                              float* __restrict__ out) {
    __shared__ float xs[NB * ND];
    for (int i = threadIdx.x; i < NB * ND; i += 256) xs[i] = xf[i];
    __syncthreads();
    int warp = threadIdx.x >> 5, lane = threadIdx.x & 31;
    int vtok = blockIdx.x * 8 + warp;
    if (vtok < NV) {
        const float* wrow = wte + (long long)vtok * ND;
        float a0 = 0.f, a1 = 0.f, a2 = 0.f, a3 = 0.f;
        for (int d = lane; d < ND; d += 32) {
            float w = wrow[d];
            a0 += w * xs[d];
            a1 += w * xs[ND + d];
            a2 += w * xs[2 * ND + d];
            a3 += w * xs[3 * ND + d];
        }
#pragma unroll
        for (int o = 16; o > 0; o >>= 1) {
            a0 += __shfl_down_sync(0xffffffffu, a0, o);
            a1 += __shfl_down_sync(0xffffffffu, a1, o);
            a2 += __shfl_down_sync(0xffffffffu, a2, o);
            a3 += __shfl_down_sync(0xffffffffu, a3, o);
        }
        if (lane == 0) {
            out[0 * NV + vtok] = a0;
            out[1 * NV + vtok] = a1;
            out[2 * NV + vtok] = a2;
            out[3 * NV + vtok] = a3;
        }
    }
}

// ---------------- host-side orchestration ------------------------------------
extern "C" void kernel_launch(void* const* d_in, const int* in_sizes, int n_in,
                              void* d_out, int out_size) {
    (void)in_sizes; (void)n_in; (void)out_size;
    const int*   idx         = (const int*)d_in[0];
    const float* wte         = (const float*)d_in[1];
    const float* wpe         = (const float*)d_in[2];
    const float* ln1_w       = (const float*)d_in[3];
    const float* attn_w      = (const float*)d_in[4];
    const float* attn_proj_w = (const float*)d_in[5];
    const float* ln2_w       = (const float*)d_in[6];
    const float* router_w    = (const float*)d_in[7];
    const float* fc_w        = (const float*)d_in[8];
    const float* proj_w      = (const float*)d_in[9];
    const float* lnf_w       = (const float*)d_in[10];
    float* out = (float*)d_out;

    void *p0, *p1, *p2, *p3, *p4, *p5, *p6, *p7, *p8, *p9;
    cudaGetSymbolAddress(&p0, g_x);
    cudaGetSymbolAddress(&p1, g_xn);
    cudaGetSymbolAddress(&p2, g_qkv);
    cudaGetSymbolAddress(&p3, g_S);
    cudaGetSymbolAddress(&p4, g_att);
    cudaGetSymbolAddress(&p5, g_h);
    cudaGetSymbolAddress(&p6, g_probs);
    cudaGetSymbolAddress(&p7, g_wsel);
    cudaGetSymbolAddress(&p8, g_sel);
    cudaGetSymbolAddress(&p9, g_xf);
    float* x     = (float*)p0;
    float* xn    = (float*)p1;
    float* qkv   = (float*)p2;
    float* S     = (float*)p3;
    float* att   = (float*)p4;
    float* h     = (float*)p5;
    float* probs = (float*)p6;
    float* wsel  = (float*)p7;
    int*   sel   = (int*)p8;
    float* xf    = (float*)p9;

    embed_kernel<<<NTOK, 256>>>(idx, wte, wpe, x);

    for (int l = 0; l < NL; l++) {
        const float* ln1 = ln1_w + l * ND;
        const float* aw  = attn_w + (long long)l * 3 * ND * ND;
        const float* apw = attn_proj_w + (long long)l * ND * ND;
        const float* ln2 = ln2_w + l * ND;
        const float* rw  = router_w + (long long)l * NE * ND;
        const float* fw  = fc_w + (long long)l * NE * NDFF * ND;
        const float* pjw = proj_w + (long long)l * NE * ND * NDFF;

        // ---- attention block ----
        rmsnorm_kernel<<<NTOK, 256>>>(x, ln1, xn, 1, 0);
        // qkv = xn @ attn_w^T : [4096, 3072]
        gemm_kernel<<<dim3(3 * ND / BN, NTOK / BM, 1), 256>>>(
            xn, aw, qkv, NTOK, 3 * ND, ND, ND, ND, 3 * ND,
            0, 0, 0, 0, 0, 0, 1, 1.0f,
            nullptr, nullptr, 0, 0, nullptr, nullptr, nullptr);
        // S = (Q K^T)/8 per (b,h)
        gemm_kernel<<<dim3(NT / BN, NT / BM, NB * NH), 256>>>(
            qkv, qkv + ND, S, NT, NT, NHD, 3 * ND, 3 * ND, NT,
            (long long)NT * 3 * ND, NHD, (long long)NT * 3 * ND, NHD,
            (long long)NH * NT * NT, (long long)NT * NT, NH, 0.125f,
            nullptr, nullptr, 0, 0, nullptr, nullptr, nullptr);
        softmax_kernel<<<dim3(NT, NB * NH), 128>>>(S);
        // att = P V per (b,h)   (V is K-major -> transB=1)
        gemm_kernel<<<dim3(1, NT / BM, NB * NH), 256>>>(
            S, qkv + 2 * ND, att, NT, NHD, NT, NT, 3 * ND, ND,
            (long long)NH * NT * NT, (long long)NT * NT,
            (long long)NT * 3 * ND, NHD,
            (long long)NT * ND, NHD, NH, 1.0f,
            nullptr, nullptr, 1, 0, nullptr, nullptr, nullptr);
        // x = x + att @ attn_proj^T
        gemm_kernel<<<dim3(ND / BN, NTOK / BM, 1), 256>>>(
            att, apw, x, NTOK, ND, ND, ND, ND, ND,
            0, 0, 0, 0, 0, 0, 1, 1.0f,
            x, nullptr, 0, 0, nullptr, nullptr, nullptr);

        // ---- MoE block ----
        rmsnorm_kernel<<<NTOK, 256>>>(x, ln2, xn, 1, 0);
        router_kernel<<<NTOK, 128>>>(xn, rw, probs);
        topk_kernel<<<NE, 1024>>>(probs, sel, wsel);
        // h[e] = gelu( xn[sel[e]] @ fc_w[e]^T ) : [1024, 4096] per expert
        gemm_kernel<<<dim3(NDFF / BN, NTOPK / BM, NE), 256>>>(
            xn, fw, h, NTOPK, NDFF, ND, ND, ND, NDFF,
            0, 0, (long long)NDFF * ND, 0, (long long)NTOPK * NDFF, 0, 1, 1.0f,
            nullptr, sel, 0, 1, nullptr, nullptr, nullptr);
        // x[sel[e,k]] += w[e,k] * (h[e] @ proj_w[e]^T)
        gemm_kernel<<<dim3(ND / BN, NTOPK / BM, NE), 256>>>(
            h, pjw, nullptr, NTOPK, ND, NDFF, NDFF, NDFF, ND,
            (long long)NTOPK * NDFF, 0, (long long)ND * NDFF, 0, 0, 0, 1, 1.0f,
            nullptr, nullptr, 0, 2, sel, wsel, x);
    }

    // final rmsnorm only on the 4 last-position rows, then tied LM head
    rmsnorm_kernel<<<NB, 256>>>(x, lnf_w, xf, NT, NT - 1);
    lmhead_kernel<<<(NV + 7) / 8, 256>>>(xf, wte, out);
}

// round 8
// speedup vs baseline: 2.1725x; 1.8843x over previous
#include <cuda_runtime.h>
#include <cuda_bf16.h>
#include <math.h>
#include <stdint.h>

#define NB 4
#define NT 1024
#define ND 1024
#define NH 16
#define NL 2
#define NE 8
#define NDFF 4096
#define NV 50257
#define NHD 64
#define NTOK 4096   // NB*NT
#define NTOPK 1024  // CAP*NB*NT/NE

// ---------------- scratch (static device allocations; no cudaMalloc) ----------
__device__ float g_x[NTOK * ND];
__device__ float g_xn[NTOK * ND];
__device__ float g_qkv[NTOK * 3 * ND];
__device__ float g_S[(size_t)NB * NH * NT * NT];       // 268 MB attention scores
__device__ float g_att[NTOK * ND];
__device__ float g_h[(size_t)NE * NTOPK * NDFF];       // 134 MB MoE hidden
__device__ float g_probs[NTOK * NE];
__device__ float g_wsel[NE * NTOPK];
__device__ int   g_sel[NE * NTOPK];
__device__ float g_xf[NB * ND];

// ---------------- embedding ---------------------------------------------------
__global__ void embed_kernel(const int* __restrict__ idx, const float* __restrict__ wte,
                             const float* __restrict__ wpe, float* __restrict__ x) {
    int n = blockIdx.x;
    int t = n & (NT - 1);
    long long r = idx[n];
    const float* a = wte + r * ND;
    const float* b = wpe + (long long)t * ND;
    float* o = x + (long long)n * ND;
    for (int d = threadIdx.x; d < ND; d += blockDim.x) o[d] = a[d] + b[d];
}

// ---------------- rmsnorm -----------------------------------------------------
__global__ void rmsnorm_kernel(const float* __restrict__ x, const float* __restrict__ w,
                               float* __restrict__ out, int rowMul, int rowAdd) {
    int orow = blockIdx.x;
    long long irow = (long long)orow * rowMul + rowAdd;
    const float* xr = x + irow * ND;
    __shared__ float red[256];
    float s = 0.f;
    for (int d = threadIdx.x; d < ND; d += 256) { float v = xr[d]; s += v * v; }
    red[threadIdx.x] = s; __syncthreads();
    for (int o = 128; o > 0; o >>= 1) {
        if (threadIdx.x < o) red[threadIdx.x] += red[threadIdx.x + o];
        __syncthreads();
    }
    float scale = 1.0f / sqrtf(red[0] * (1.0f / ND) + 1e-6f);
    float* o = out + (long long)orow * ND;
    for (int d = threadIdx.x; d < ND; d += 256) o[d] = xr[d] * scale * w[d];
}

// ---------------- tensor-core batched GEMM (split-bf16, fp32-accurate) --------
// Requirements exploited by every call site: K % 32 == 0, M % 128 == 0,
// (transB=0 => N % 128 == 0). N guard kept for transB=1 (PV GEMM, N=64).
#define BM 128
#define BN 128
#define BK 32
#define LDS_PAD 40   // 80B rows: 16B-aligned for ldmatrix; conflict-free pattern

__device__ __forceinline__ void mma_bf16(float* c, const uint32_t* a,
                                         uint32_t b0, uint32_t b1) {
    asm volatile(
        "mma.sync.aligned.m16n8k16.row.col.f32.bf16.bf16.f32 "
        "{%0,%1,%2,%3}, {%4,%5,%6,%7}, {%8,%9}, {%0,%1,%2,%3};"
        : "+f"(c[0]), "+f"(c[1]), "+f"(c[2]), "+f"(c[3])
        : "r"(a[0]), "r"(a[1]), "r"(a[2]), "r"(a[3]), "r"(b0), "r"(b1));
}

__device__ __forceinline__ void ldsm_x4(uint32_t* r, uint32_t addr) {
    asm volatile("ldmatrix.sync.aligned.m8n8.x4.shared.b16 {%0,%1,%2,%3}, [%4];"
                 : "=r"(r[0]), "=r"(r[1]), "=r"(r[2]), "=r"(r[3]) : "r"(addr));
}

__device__ __forceinline__ uint32_t smem_u32(const void* p) {
    return (uint32_t)__cvta_generic_to_shared(p);
}

// split x,y into hi/lo bf16 pairs packed as bf16x2 words
__device__ __forceinline__ void split2(float x, float y, uint32_t& h, uint32_t& l) {
    __nv_bfloat16 hx = __float2bfloat16(x), hy = __float2bfloat16(y);
    __nv_bfloat16 lx = __float2bfloat16(x - __bfloat162float(hx));
    __nv_bfloat16 ly = __float2bfloat16(y - __bfloat162float(hy));
    uint16_t uhx = *(uint16_t*)&hx, uhy = *(uint16_t*)&hy;
    uint16_t ulx = *(uint16_t*)&lx, uly = *(uint16_t*)&ly;
    h = ((uint32_t)uhy << 16) | uhx;
    l = ((uint32_t)uly << 16) | ulx;
}

__global__ __launch_bounds__(256) void gemm_kernel(
    const float* __restrict__ A, const float* __restrict__ B, float* __restrict__ C,
    int M, int N, int K, int lda, int ldb, int ldc,
    long long sA1, long long sA2, long long sB1, long long sB2,
    long long sC1, long long sC2, int zdiv, float alpha,
    const float* __restrict__ residual, const int* __restrict__ rowsA,
    int transB, int epilogue,
    const int* __restrict__ rowsOut, const float* __restrict__ rowScale,
    float* __restrict__ scatter)
{
    __shared__ __nv_bfloat16 AsH[BM][LDS_PAD];
    __shared__ __nv_bfloat16 AsL[BM][LDS_PAD];
    __shared__ __nv_bfloat16 BsH[BN][LDS_PAD];
    __shared__ __nv_bfloat16 BsL[BN][LDS_PAD];

    int z = blockIdx.z;
    int z1 = z / zdiv, z2 = z - z1 * zdiv;
    A += z1 * sA1 + z2 * sA2;
    B += z1 * sB1 + z2 * sB2;
    if (C) C += z1 * sC1 + z2 * sC2;

    int m0 = blockIdx.y * BM, n0 = blockIdx.x * BN;
    int tid = threadIdx.x;
    int lane = tid & 31;
    int warpId = tid >> 5;
    int wm = (warpId & 3) * 32;   // warp m-offset within block tile
    int wn = (warpId >> 2) * 64;  // warp n-offset within block tile

    float acc[2][8][4];
#pragma unroll
    for (int mi = 0; mi < 2; mi++)
#pragma unroll
        for (int ni = 0; ni < 8; ni++)
#pragma unroll
            for (int t = 0; t < 4; t++) acc[mi][ni][t] = 0.f;

    // ---- global loader mappings ----
    // A: thread -> row am, k half kbA, 4x float4
    int am = tid >> 1, kbA = (tid & 1) * 16;
    long long arow = m0 + am;
    if (rowsA) arow = rowsA[(long long)z * M + m0 + am];
    const float* aPtr = A + arow * (long long)lda + kbA;

    // B (transB=0): row bn, k half kbB ; B (transB=1): k row bk, n chunk bnb
    int bn = tid >> 1, kbB = (tid & 1) * 16;
    int bk = tid >> 3, bnb = (tid & 7) * 16;
    const float* bPtr0 = B + (long long)(n0 + bn) * ldb + kbB;     // transB=0
    const float* bPtr1 = B + (long long)bk * ldb + n0 + bnb;       // transB=1

    float4 av[4], bv[4];

    // ---- prefetch tile 0 ----
#pragma unroll
    for (int j = 0; j < 4; j++) av[j] = *(const float4*)(aPtr + 4 * j);
    if (!transB) {
#pragma unroll
        for (int j = 0; j < 4; j++) bv[j] = *(const float4*)(bPtr0 + 4 * j);
    } else {
#pragma unroll
        for (int j = 0; j < 4; j++) {
            int nn = n0 + bnb + 4 * j;
            bv[j] = (nn < N) ? *(const float4*)(bPtr1 + 4 * j)
                             : make_float4(0.f, 0.f, 0.f, 0.f);
        }
    }

    for (int k0 = 0; k0 < K; k0 += BK) {
        // ---- split + store staged tile to smem ----
#pragma unroll
        for (int j = 0; j < 4; j++) {
            uint32_t h0, l0, h1, l1;
            split2(av[j].x, av[j].y, h0, l0);
            split2(av[j].z, av[j].w, h1, l1);
            int kk = kbA + 4 * j;
            *(uint32_t*)&AsH[am][kk] = h0;
            *(uint32_t*)&AsL[am][kk] = l0;
            *(uint32_t*)&AsH[am][kk + 2] = h1;
            *(uint32_t*)&AsL[am][kk + 2] = l1;
        }
        if (!transB) {
#pragma unroll
            for (int j = 0; j < 4; j++) {
                uint32_t h0, l0, h1, l1;
                split2(bv[j].x, bv[j].y, h0, l0);
                split2(bv[j].z, bv[j].w, h1, l1);
                int kk = kbB + 4 * j;
                *(uint32_t*)&BsH[bn][kk] = h0;
                *(uint32_t*)&BsL[bn][kk] = l0;
                *(uint32_t*)&BsH[bn][kk + 2] = h1;
                *(uint32_t*)&BsL[bn][kk + 2] = l1;
            }
        } else {
#pragma unroll
            for (int j = 0; j < 4; j++) {
                float vv[4] = {bv[j].x, bv[j].y, bv[j].z, bv[j].w};
#pragma unroll
                for (int t = 0; t < 4; t++) {
                    int nn = bnb + 4 * j + t;
                    __nv_bfloat16 h = __float2bfloat16(vv[t]);
                    BsH[nn][bk] = h;
                    BsL[nn][bk] = __float2bfloat16(vv[t] - __bfloat162float(h));
                }
            }
        }
        __syncthreads();

        // ---- issue prefetch for next tile (hidden behind MMA phase) ----
        if (k0 + BK < K) {
            const float* ap = aPtr + k0 + BK;
#pragma unroll
            for (int j = 0; j < 4; j++) av[j] = *(const float4*)(ap + 4 * j);
            if (!transB) {
                const float* bp = bPtr0 + k0 + BK;
#pragma unroll
                for (int j = 0; j < 4; j++) bv[j] = *(const float4*)(bp + 4 * j);
            } else {
                const float* bp = bPtr1 + (long long)(k0 + BK) * ldb;
#pragma unroll
                for (int j = 0; j < 4; j++) {
                    int nn = n0 + bnb + 4 * j;
                    bv[j] = (nn < N) ? *(const float4*)(bp + 4 * j)
                                     : make_float4(0.f, 0.f, 0.f, 0.f);
                }
            }
        }

        // ---- tensor-core inner product: 2 k16 steps, ldmatrix fragments ----
        int arl = lane & 15;             // A ldmatrix row-lane
        int acl = (lane >> 4) * 8;       // A ldmatrix col offset
        int brl = (lane & 7) + ((lane & 16) >> 1);  // B ldmatrix row-lane
#pragma unroll
        for (int ks = 0; ks < 2; ks++) {
            int kk = ks * 16;
            uint32_t ah[2][4], al[2][4];
#pragma unroll
            for (int mi = 0; mi < 2; mi++) {
                int r0 = wm + mi * 16;
                ldsm_x4(ah[mi], smem_u32(&AsH[r0 + arl][kk + acl]));
                ldsm_x4(al[mi], smem_u32(&AsL[r0 + arl][kk + acl]));
            }
            int bcl = kk + (lane & 8);
#pragma unroll
            for (int nip = 0; nip < 4; nip++) {
                int cn = wn + nip * 16;
                uint32_t bh[4], bl[4];
                ldsm_x4(bh, smem_u32(&BsH[cn + brl][bcl]));
                ldsm_x4(bl, smem_u32(&BsL[cn + brl][bcl]));
#pragma unroll
                for (int mi = 0; mi < 2; mi++) {
                    mma_bf16(acc[mi][2 * nip], ah[mi], bh[0], bh[1]);
                    mma_bf16(acc[mi][2 * nip], ah[mi], bl[0], bl[1]);
                    mma_bf16(acc[mi][2 * nip], al[mi], bh[0], bh[1]);
                    mma_bf16(acc[mi][2 * nip + 1], ah[mi], bh[2], bh[3]);
                    mma_bf16(acc[mi][2 * nip + 1], ah[mi], bl[2], bl[3]);
                    mma_bf16(acc[mi][2 * nip + 1], al[mi], bh[2], bh[3]);
                }
            }
        }
        __syncthreads();
    }

    // ---- epilogue ----
    int fr = lane >> 2;
    int fc = (lane & 3) * 2;
#pragma unroll
    for (int mi = 0; mi < 2; mi++) {
#pragma unroll
        for (int ni = 0; ni < 8; ni++) {
            int mBase = m0 + wm + mi * 16 + fr;
            int nBase = n0 + wn + ni * 8 + fc;
#pragma unroll
            for (int half = 0; half < 2; half++) {
                int m = mBase + half * 8;
                if (m >= M) continue;
#pragma unroll
                for (int t = 0; t < 2; t++) {
                    int n = nBase + t;
                    if (n >= N) continue;
                    float v = acc[mi][ni][half * 2 + t] * alpha;
                    if (epilogue == 0) {
                        if (residual) v += residual[(long long)m * ldc + n];
                        C[(long long)m * ldc + n] = v;
                    } else if (epilogue == 1) {
                        C[(long long)m * ldc + n] =
                            0.5f * v * (1.0f + erff(v * 0.70710678118654752440f));
                    } else {
                        long long rr = rowsOut[(long long)z * M + m];
                        float wsc = rowScale[(long long)z * M + m];
                        atomicAdd(&scatter[rr * ldc + n], wsc * v);
                    }
                }
            }
        }
    }
}

// ---------------- causal softmax on score rows -------------------------------
__global__ void softmax_kernel(float* __restrict__ S) {
    int q = blockIdx.x;
    long long z = blockIdx.y;
    float* row = S + z * (long long)NT * NT + (long long)q * NT;
    int len = q + 1;
    __shared__ float red[128];
    int tid = threadIdx.x;
    float mx = -1e30f;
    for (int i = tid; i < len; i += 128) mx = fmaxf(mx, row[i]);
    red[tid] = mx; __syncthreads();
    for (int o = 64; o > 0; o >>= 1) {
        if (tid < o) red[tid] = fmaxf(red[tid], red[tid + o]);
        __syncthreads();
    }
    mx = red[0]; __syncthreads();
    float s = 0.f;
    for (int i = tid; i < len; i += 128) { float e = expf(row[i] - mx); row[i] = e; s += e; }
    red[tid] = s; __syncthreads();
    for (int o = 64; o > 0; o >>= 1) {
        if (tid < o) red[tid] += red[tid + o];
        __syncthreads();
    }
    float inv = 1.0f / red[0];
    for (int i = tid; i < len; i += 128) row[i] *= inv;
    for (int i = len + tid; i < NT; i += 128) row[i] = 0.f;  // zero masked region for PV gemm
}

// ---------------- router logits + softmax over experts -----------------------
__global__ void router_kernel(const float* __restrict__ xn, const float* __restrict__ wr,
                              float* __restrict__ probs) {
    int n = blockIdx.x;
    const float* xr = xn + (long long)n * ND;
    float acc[NE];
#pragma unroll
    for (int e = 0; e < NE; e++) acc[e] = 0.f;
    for (int d = threadIdx.x; d < ND; d += 128) {
        float xv = xr[d];
#pragma unroll
        for (int e = 0; e < NE; e++) acc[e] += xv * wr[e * ND + d];
    }
    __shared__ float red[128];
    __shared__ float logit[NE];
    for (int e = 0; e < NE; e++) {
        red[threadIdx.x] = acc[e]; __syncthreads();
        for (int o = 64; o > 0; o >>= 1) {
            if (threadIdx.x < o) red[threadIdx.x] += red[threadIdx.x + o];
            __syncthreads();
        }
        if (threadIdx.x == 0) logit[e] = red[0];
        __syncthreads();
    }
    if (threadIdx.x == 0) {
        float mx = logit[0];
        for (int e = 1; e < NE; e++) mx = fmaxf(mx, logit[e]);
        float s = 0.f; float ex[NE];
        for (int e = 0; e < NE; e++) { ex[e] = expf(logit[e] - mx); s += ex[e]; }
        float inv = 1.0f / s;
        for (int e = 0; e < NE; e++) probs[(long long)n * NE + e] = ex[e] * inv;
    }
}

// ---------------- per-expert top-k via in-smem bitonic sort -------------------
__global__ void topk_kernel(const float* __restrict__ probs, int* __restrict__ sel,
                            float* __restrict__ weights) {
    int e = blockIdx.x;
    __shared__ float v[NTOK];
    __shared__ int ix[NTOK];
    int tid = threadIdx.x;
    for (int i = tid; i < NTOK; i += 1024) { v[i] = probs[(long long)i * NE + e]; ix[i] = i; }
    __syncthreads();
    for (int k = 2; k <= NTOK; k <<= 1) {
        for (int j = k >> 1; j > 0; j >>= 1) {
            for (int i = tid; i < NTOK; i += 1024) {
                int p = i ^ j;
                if (p > i) {
                    float va = v[i], vb = v[p];
                    int ia = ix[i], ib = ix[p];
                    bool sw;
                    if ((i & k) == 0) sw = (vb > va) || (vb == va && ib < ia);
                    else              sw = (va > vb) || (va == vb && ia < ib);
                    if (sw) { v[i] = vb; v[p] = va; ix[i] = ib; ix[p] = ia; }
                }
            }
            __syncthreads();
        }
    }
    for (int i = tid; i < NTOPK; i += 1024) {
        sel[e * NTOPK + i] = ix[i];
        weights[e * NTOPK + i] = v[i];
    }
}

// ---------------- LM head: logits for last token of each batch ----------------
__global__ void lmhead_kernel(const float* __restrict__ xf, const float* __restrict__ wte,
                              float* __restrict__ out) {
    __shared__ float xs[NB * ND];
    for (int i = threadIdx.x; i < NB * ND; i += 256) xs[i] = xf[i];
    __syncthreads();
    int warp = threadIdx.x >> 5, lane = threadIdx.x & 31;
    int vtok = blockIdx.x * 8 + warp;
    if (vtok < NV) {
        const float* wrow = wte + (long long)vtok * ND;
        float a0 = 0.f, a1 = 0.f, a2 = 0.f, a3 = 0.f;
        for (int d = lane; d < ND; d += 32) {
            float w = wrow[d];
            a0 += w * xs[d];
            a1 += w * xs[ND + d];
            a2 += w * xs[2 * ND + d];
            a3 += w * xs[3 * ND + d];
        }
#pragma unroll
        for (int o = 16; o > 0; o >>= 1) {
            a0 += __shfl_down_sync(0xffffffffu, a0, o);
            a1 += __shfl_down_sync(0xffffffffu, a1, o);
            a2 += __shfl_down_sync(0xffffffffu, a2, o);
            a3 += __shfl_down_sync(0xffffffffu, a3, o);
        }
        if (lane == 0) {
            out[0 * NV + vtok] = a0;
            out[1 * NV + vtok] = a1;
            out[2 * NV + vtok] = a2;
            out[3 * NV + vtok] = a3;
        }
    }
}

// ---------------- host-side orchestration ------------------------------------
extern "C" void kernel_launch(void* const* d_in, const int* in_sizes, int n_in,
                              void* d_out, int out_size) {
    (void)in_sizes; (void)n_in; (void)out_size;
    const int*   idx         = (const int*)d_in[0];
    const float* wte         = (const float*)d_in[1];
    const float* wpe         = (const float*)d_in[2];
    const float* ln1_w       = (const float*)d_in[3];
    const float* attn_w      = (const float*)d_in[4];
    const float* attn_proj_w = (const float*)d_in[5];
    const float* ln2_w       = (const float*)d_in[6];
    const float* router_w    = (const float*)d_in[7];
    const float* fc_w        = (const float*)d_in[8];
    const float* proj_w      = (const float*)d_in[9];
    const float* lnf_w       = (const float*)d_in[10];
    float* out = (float*)d_out;

    void *p0, *p1, *p2, *p3, *p4, *p5, *p6, *p7, *p8, *p9;
    cudaGetSymbolAddress(&p0, g_x);
    cudaGetSymbolAddress(&p1, g_xn);
    cudaGetSymbolAddress(&p2, g_qkv);
    cudaGetSymbolAddress(&p3, g_S);
    cudaGetSymbolAddress(&p4, g_att);
    cudaGetSymbolAddress(&p5, g_h);
    cudaGetSymbolAddress(&p6, g_probs);
    cudaGetSymbolAddress(&p7, g_wsel);
    cudaGetSymbolAddress(&p8, g_sel);
    cudaGetSymbolAddress(&p9, g_xf);
    float* x     = (float*)p0;
    float* xn    = (float*)p1;
    float* qkv   = (float*)p2;
    float* S     = (float*)p3;
    float* att   = (float*)p4;
    float* h     = (float*)p5;
    float* probs = (float*)p6;
    float* wsel  = (float*)p7;
    int*   sel   = (int*)p8;
    float* xf    = (float*)p9;

    embed_kernel<<<NTOK, 256>>>(idx, wte, wpe, x);

    for (int l = 0; l < NL; l++) {
        const float* ln1 = ln1_w + l * ND;
        const float* aw  = attn_w + (long long)l * 3 * ND * ND;
        const float* apw = attn_proj_w + (long long)l * ND * ND;
        const float* ln2 = ln2_w + l * ND;
        const float* rw  = router_w + (long long)l * NE * ND;
        const float* fw  = fc_w + (long long)l * NE * NDFF * ND;
        const float* pjw = proj_w + (long long)l * NE * ND * NDFF;

        // ---- attention block ----
        rmsnorm_kernel<<<NTOK, 256>>>(x, ln1, xn, 1, 0);
        // qkv = xn @ attn_w^T : [4096, 3072]
        gemm_kernel<<<dim3(3 * ND / BN, NTOK / BM, 1), 256>>>(
            xn, aw, qkv, NTOK, 3 * ND, ND, ND, ND, 3 * ND,
            0, 0, 0, 0, 0, 0, 1, 1.0f,
            nullptr, nullptr, 0, 0, nullptr, nullptr, nullptr);
        // S = (Q K^T)/8 per (b,h)
        gemm_kernel<<<dim3(NT / BN, NT / BM, NB * NH), 256>>>(
            qkv, qkv + ND, S, NT, NT, NHD, 3 * ND, 3 * ND, NT,
            (long long)NT * 3 * ND, NHD, (long long)NT * 3 * ND, NHD,
            (long long)NH * NT * NT, (long long)NT * NT, NH, 0.125f,
            nullptr, nullptr, 0, 0, nullptr, nullptr, nullptr);
        softmax_kernel<<<dim3(NT, NB * NH), 128>>>(S);
        // att = P V per (b,h)   (V is K-major -> transB=1)
        gemm_kernel<<<dim3(1, NT / BM, NB * NH), 256>>>(
            S, qkv + 2 * ND, att, NT, NHD, NT, NT, 3 * ND, ND,
            (long long)NH * NT * NT, (long long)NT * NT,
            (long long)NT * 3 * ND, NHD,
            (long long)NT * ND, NHD, NH, 1.0f,
            nullptr, nullptr, 1, 0, nullptr, nullptr, nullptr);
        // x = x + att @ attn_proj^T
        gemm_kernel<<<dim3(ND / BN, NTOK / BM, 1), 256>>>(
            att, apw, x, NTOK, ND, ND, ND, ND, ND,
            0, 0, 0, 0, 0, 0, 1, 1.0f,
            x, nullptr, 0, 0, nullptr, nullptr, nullptr);

        // ---- MoE block ----
        rmsnorm_kernel<<<NTOK, 256>>>(x, ln2, xn, 1, 0);
        router_kernel<<<NTOK, 128>>>(xn, rw, probs);
        topk_kernel<<<NE, 1024>>>(probs, sel, wsel);
        // h[e] = gelu( xn[sel[e]] @ fc_w[e]^T ) : [1024, 4096] per expert
        gemm_kernel<<<dim3(NDFF / BN, NTOPK / BM, NE), 256>>>(
            xn, fw, h, NTOPK, NDFF, ND, ND, ND, NDFF,
            0, 0, (long long)NDFF * ND, 0, (long long)NTOPK * NDFF, 0, 1, 1.0f,
            nullptr, sel, 0, 1, nullptr, nullptr, nullptr);
        // x[sel[e,k]] += w[e,k] * (h[e] @ proj_w[e]^T)
        gemm_kernel<<<dim3(ND / BN, NTOPK / BM, NE), 256>>>(
            h, pjw, nullptr, NTOPK, ND, NDFF, NDFF, NDFF, ND,
            (long long)NTOPK * NDFF, 0, (long long)ND * NDFF, 0, 0, 0, 1, 1.0f,
            nullptr, nullptr, 0, 2, sel, wsel, x);
    }

    // final rmsnorm only on the 4 last-position rows, then tied LM head
    rmsnorm_kernel<<<NB, 256>>>(x, lnf_w, xf, NT, NT - 1);
    lmhead_kernel<<<(NV + 7) / 8, 256>>>(xf, wte, out);
}

// round 9
// speedup vs baseline: 2.9242x; 1.3460x over previous
#include <cuda_runtime.h>
#include <cuda_bf16.h>
#include <math.h>
#include <stdint.h>

#define NB 4
#define NT 1024
#define ND 1024
#define NH 16
#define NL 2
#define NE 8
#define NDFF 4096
#define NV 50257
#define NHD 64
#define NTOK 4096   // NB*NT
#define NTOPK 1024  // CAP*NB*NT/NE

// ---------------- scratch (static device allocations; no cudaMalloc) ----------
__device__ float g_x[NTOK * ND];
__device__ float g_xn[NTOK * ND];           // fp32 xn (router input)
__device__ float g_S[(size_t)NB * NH * NT * NT];
__device__ float g_probs[NTOK * NE];
__device__ float g_wsel[NE * NTOPK];
__device__ int   g_sel[NE * NTOPK];
__device__ float g_xf[NB * ND];

// split bf16 activations
__device__ __nv_bfloat16 g_xnH[NTOK * ND],  g_xnL[NTOK * ND];
__device__ __nv_bfloat16 g_qkvH[NTOK * 3 * ND], g_qkvL[NTOK * 3 * ND];  // V region unused
__device__ __nv_bfloat16 g_VtH[(NB * NH * NHD + 128) * NT], g_VtL[(NB * NH * NHD + 128) * NT];
__device__ __nv_bfloat16 g_PH[(size_t)NB * NH * NT * NT], g_PL[(size_t)NB * NH * NT * NT];
__device__ __nv_bfloat16 g_attH[NTOK * ND], g_attL[NTOK * ND];
__device__ __nv_bfloat16 g_hH[(size_t)NE * NTOPK * NDFF], g_hL[(size_t)NE * NTOPK * NDFF];

// split bf16 weights
__device__ __nv_bfloat16 g_awH[NL * 3 * ND * ND],  g_awL[NL * 3 * ND * ND];
__device__ __nv_bfloat16 g_apwH[NL * ND * ND],     g_apwL[NL * ND * ND];
__device__ __nv_bfloat16 g_fwH[(size_t)NL * NE * NDFF * ND], g_fwL[(size_t)NL * NE * NDFF * ND];
__device__ __nv_bfloat16 g_pjwH[(size_t)NL * NE * ND * NDFF], g_pjwL[(size_t)NL * NE * ND * NDFF];

// ---------------- helpers ------------------------------------------------------
__device__ __forceinline__ void store_split(float v, __nv_bfloat16* ph, __nv_bfloat16* pl) {
    __nv_bfloat16 h = __float2bfloat16(v);
    *ph = h;
    *pl = __float2bfloat16(v - __bfloat162float(h));
}

__device__ __forceinline__ uint32_t smem_u32(const void* p) {
    return (uint32_t)__cvta_generic_to_shared(p);
}

__device__ __forceinline__ void cp16(void* dst_smem, const void* src) {
    asm volatile("cp.async.cg.shared.global [%0], [%1], 16;"
                 :: "r"(smem_u32(dst_smem)), "l"(src));
}
#define CP_COMMIT() asm volatile("cp.async.commit_group;")
#define CP_WAIT0()  asm volatile("cp.async.wait_group 0;")

__device__ __forceinline__ void mma_bf16(float* c, const uint32_t* a,
                                         uint32_t b0, uint32_t b1) {
    asm volatile(
        "mma.sync.aligned.m16n8k16.row.col.f32.bf16.bf16.f32 "
        "{%0,%1,%2,%3}, {%4,%5,%6,%7}, {%8,%9}, {%0,%1,%2,%3};"
        : "+f"(c[0]), "+f"(c[1]), "+f"(c[2]), "+f"(c[3])
        : "r"(a[0]), "r"(a[1]), "r"(a[2]), "r"(a[3]), "r"(b0), "r"(b1));
}

__device__ __forceinline__ void ldsm_x4(uint32_t* r, uint32_t addr) {
    asm volatile("ldmatrix.sync.aligned.m8n8.x4.shared.b16 {%0,%1,%2,%3}, [%4];"
                 : "=r"(r[0]), "=r"(r[1]), "=r"(r[2]), "=r"(r[3]) : "r"(addr));
}

// ---------------- fp32 -> (hi, lo) bf16 conversion ----------------------------
__global__ void split_kernel(const float* __restrict__ src, __nv_bfloat16* __restrict__ h,
                             __nv_bfloat16* __restrict__ l, int n4) {
    int i = blockIdx.x * blockDim.x + threadIdx.x;
    if (i < n4) {
        float4 v = ((const float4*)src)[i];
        int b = i * 4;
        store_split(v.x, h + b, l + b);
        store_split(v.y, h + b + 1, l + b + 1);
        store_split(v.z, h + b + 2, l + b + 2);
        store_split(v.w, h + b + 3, l + b + 3);
    }
}

// ---------------- embedding ---------------------------------------------------
__global__ void embed_kernel(const int* __restrict__ idx, const float* __restrict__ wte,
                             const float* __restrict__ wpe, float* __restrict__ x) {
    int n = blockIdx.x;
    int t = n & (NT - 1);
    long long r = idx[n];
    const float* a = wte + r * ND;
    const float* b = wpe + (long long)t * ND;
    float* o = x + (long long)n * ND;
    for (int d = threadIdx.x; d < ND; d += blockDim.x) o[d] = a[d] + b[d];
}

// ---------------- rmsnorm (fp32 and/or split-bf16 output) ---------------------
__global__ void rmsnorm_kernel(const float* __restrict__ x, const float* __restrict__ w,
                               float* __restrict__ outF,
                               __nv_bfloat16* __restrict__ outH,
                               __nv_bfloat16* __restrict__ outL,
                               int rowMul, int rowAdd) {
    int orow = blockIdx.x;
    long long irow = (long long)orow * rowMul + rowAdd;
    const float* xr = x + irow * ND;
    __shared__ float red[256];
    float s = 0.f;
    for (int d = threadIdx.x; d < ND; d += 256) { float v = xr[d]; s += v * v; }
    red[threadIdx.x] = s; __syncthreads();
    for (int o = 128; o > 0; o >>= 1) {
        if (threadIdx.x < o) red[threadIdx.x] += red[threadIdx.x + o];
        __syncthreads();
    }
    float scale = 1.0f / sqrtf(red[0] * (1.0f / ND) + 1e-6f);
    long long ob = (long long)orow * ND;
    for (int d = threadIdx.x; d < ND; d += 256) {
        float v = xr[d] * scale * w[d];
        if (outF) outF[ob + d] = v;
        if (outH) store_split(v, outH + ob + d, outL + ob + d);
    }
}

// ---------------- tensor-core batched GEMM (pre-split bf16 operands) ----------
// C = alpha * A @ B^T with A=[M,K] via (AH,AL), B=[N,K] via (BH,BL), both row-major.
// 3-term split product: Ah*Bh + Ah*Bl + Al*Bh. cp.async double-buffered.
// epilogue: 0 fp32 store (+residual), 1 GELU->split, 2 scaled atomic scatter,
//           3 qkv special (Q,K split store; V -> transposed Vt split store),
//           4 plain split store.
#define BM 128
#define BN 128
#define BK 32
#define LDS_PAD 40
#define MT (BM * LDS_PAD)   // elems per matrix per stage
#define ST (4 * MT)         // elems per stage
#define SMEM_BYTES (2 * ST * 2)

__global__ __launch_bounds__(256, 2) void gemm_kernel(
    const __nv_bfloat16* __restrict__ AH, const __nv_bfloat16* __restrict__ AL,
    const __nv_bfloat16* __restrict__ BH, const __nv_bfloat16* __restrict__ BL,
    float* __restrict__ C, __nv_bfloat16* __restrict__ CH, __nv_bfloat16* __restrict__ CL,
    __nv_bfloat16* __restrict__ VtH, __nv_bfloat16* __restrict__ VtL,
    int M, int N, int K, int lda, int ldb, int ldc,
    long long sA1, long long sA2, long long sB1, long long sB2,
    long long sC1, long long sC2, int zdiv, float alpha,
    const float* __restrict__ residual, const int* __restrict__ rowsA,
    int epilogue, const int* __restrict__ rowsOut,
    const float* __restrict__ rowScale, float* __restrict__ scatter)
{
    extern __shared__ __nv_bfloat16 sm[];

    int z = blockIdx.z;
    int z1 = z / zdiv, z2 = z - z1 * zdiv;
    long long offA = z1 * sA1 + z2 * sA2;
    long long offB = z1 * sB1 + z2 * sB2;
    long long offC = z1 * sC1 + z2 * sC2;
    AH += offA; AL += offA;
    BH += offB; BL += offB;
    if (C)  C  += offC;
    if (CH) { CH += offC; CL += offC; }

    int m0 = blockIdx.y * BM, n0 = blockIdx.x * BN;
    int tid = threadIdx.x;
    int lane = tid & 31;
    int warpId = tid >> 5;
    int wm = (warpId & 3) * 32;
    int wn = (warpId >> 2) * 64;

    float acc[2][8][4];
#pragma unroll
    for (int mi = 0; mi < 2; mi++)
#pragma unroll
        for (int ni = 0; ni < 8; ni++)
#pragma unroll
            for (int t = 0; t < 4; t++) acc[mi][ni][t] = 0.f;

    // loader mapping: 2 threads per row, each copies 2x 16B chunks per matrix
    int am = tid >> 1, ac = (tid & 1) * 16;
    long long arow = m0 + am;
    if (rowsA) arow = rowsA[(long long)z * M + m0 + am];
    const __nv_bfloat16* gAH = AH + arow * (long long)lda + ac;
    const __nv_bfloat16* gAL = AL + arow * (long long)lda + ac;
    const __nv_bfloat16* gBH = BH + (long long)(n0 + am) * ldb + ac;
    const __nv_bfloat16* gBL = BL + (long long)(n0 + am) * ldb + ac;
    int dstA = am * LDS_PAD + ac;

    int nTiles = K / BK;

    // prologue: stage 0
    {
        __nv_bfloat16* s = sm;
        cp16(s + dstA,               gAH);
        cp16(s + dstA + 8,           gAH + 8);
        cp16(s + MT + dstA,          gAL);
        cp16(s + MT + dstA + 8,      gAL + 8);
        cp16(s + 2 * MT + dstA,      gBH);
        cp16(s + 2 * MT + dstA + 8,  gBH + 8);
        cp16(s + 3 * MT + dstA,      gBL);
        cp16(s + 3 * MT + dstA + 8,  gBL + 8);
        CP_COMMIT();
    }

    int arl = lane & 15;
    int acl = (lane >> 4) * 8;
    int brl = (lane & 7) + ((lane & 16) >> 1);

    for (int it = 0; it < nTiles; it++) {
        CP_WAIT0();
        __syncthreads();

        if (it + 1 < nTiles) {
            int k0 = (it + 1) * BK;
            __nv_bfloat16* s = sm + ((it + 1) & 1) * ST;
            cp16(s + dstA,               gAH + k0);
            cp16(s + dstA + 8,           gAH + k0 + 8);
            cp16(s + MT + dstA,          gAL + k0);
            cp16(s + MT + dstA + 8,      gAL + k0 + 8);
            cp16(s + 2 * MT + dstA,      gBH + k0);
            cp16(s + 2 * MT + dstA + 8,  gBH + k0 + 8);
            cp16(s + 3 * MT + dstA,      gBL + k0);
            cp16(s + 3 * MT + dstA + 8,  gBL + k0 + 8);
            CP_COMMIT();
        }

        const __nv_bfloat16* pAH = sm + (it & 1) * ST;
        const __nv_bfloat16* pAL = pAH + MT;
        const __nv_bfloat16* pBH = pAH + 2 * MT;
        const __nv_bfloat16* pBL = pAH + 3 * MT;

#pragma unroll
        for (int ks = 0; ks < 2; ks++) {
            int kk = ks * 16;
            uint32_t ah[2][4], al[2][4];
#pragma unroll
            for (int mi = 0; mi < 2; mi++) {
                int r0 = wm + mi * 16 + arl;
                ldsm_x4(ah[mi], smem_u32(pAH + r0 * LDS_PAD + kk + acl));
                ldsm_x4(al[mi], smem_u32(pAL + r0 * LDS_PAD + kk + acl));
            }
            int bcl = kk + (lane & 8);
#pragma unroll
            for (int nip = 0; nip < 4; nip++) {
                int cn = wn + nip * 16 + brl;
                uint32_t bh[4], bl[4];
                ldsm_x4(bh, smem_u32(pBH + cn * LDS_PAD + bcl));
                ldsm_x4(bl, smem_u32(pBL + cn * LDS_PAD + bcl));
#pragma unroll
                for (int mi = 0; mi < 2; mi++) {
                    mma_bf16(acc[mi][2 * nip], ah[mi], bh[0], bh[1]);
                    mma_bf16(acc[mi][2 * nip], ah[mi], bl[0], bl[1]);
                    mma_bf16(acc[mi][2 * nip], al[mi], bh[0], bh[1]);
                    mma_bf16(acc[mi][2 * nip + 1], ah[mi], bh[2], bh[3]);
                    mma_bf16(acc[mi][2 * nip + 1], ah[mi], bl[2], bl[3]);
                    mma_bf16(acc[mi][2 * nip + 1], al[mi], bh[2], bh[3]);
                }
            }
        }
    }

    // ---- epilogue ----
    int fr = lane >> 2;
    int fc = (lane & 3) * 2;
#pragma unroll
    for (int mi = 0; mi < 2; mi++) {
#pragma unroll
        for (int ni = 0; ni < 8; ni++) {
            int mBase = m0 + wm + mi * 16 + fr;
            int nBase = n0 + wn + ni * 8 + fc;
#pragma unroll
            for (int half = 0; half < 2; half++) {
                int m = mBase + half * 8;
                if (m >= M) continue;
#pragma unroll
                for (int t = 0; t < 2; t++) {
                    int n = nBase + t;
                    if (n >= N) continue;
                    float v = acc[mi][ni][half * 2 + t] * alpha;
                    long long ci = (long long)m * ldc + n;
                    if (epilogue == 0) {
                        if (residual) v += residual[ci];
                        C[ci] = v;
                    } else if (epilogue == 1) {
                        v = 0.5f * v * (1.0f + erff(v * 0.70710678118654752440f));
                        store_split(v, CH + ci, CL + ci);
                    } else if (epilogue == 2) {
                        long long rr = rowsOut[(long long)z * M + m];
                        atomicAdd(&scatter[rr * ldc + n],
                                  rowScale[(long long)z * M + m] * v);
                    } else if (epilogue == 3) {
                        if (n < 2 * ND) {
                            store_split(v, CH + ci, CL + ci);
                        } else {
                            int b = m >> 10, tt = m & (NT - 1);
                            int c = n - 2 * ND;
                            int h = c >> 6, d = c & (NHD - 1);
                            long long vi = ((long long)((b * NH + h) * NHD + d)) * NT + tt;
                            store_split(v, VtH + vi, VtL + vi);
                        }
                    } else {
                        store_split(v, CH + ci, CL + ci);
                    }
                }
            }
        }
    }
}

// ---------------- causal softmax: fp32 S row -> split-bf16 P row --------------
__global__ void softmax_kernel(float* __restrict__ S, __nv_bfloat16* __restrict__ PH,
                               __nv_bfloat16* __restrict__ PL) {
    int q = blockIdx.x;
    long long z = blockIdx.y;
    long long base = z * (long long)NT * NT + (long long)q * NT;
    float* row = S + base;
    int len = q + 1;
    __shared__ float red[128];
    int tid = threadIdx.x;
    float mx = -1e30f;
    for (int i = tid; i < len; i += 128) mx = fmaxf(mx, row[i]);
    red[tid] = mx; __syncthreads();
    for (int o = 64; o > 0; o >>= 1) {
        if (tid < o) red[tid] = fmaxf(red[tid], red[tid + o]);
        __syncthreads();
    }
    mx = red[0]; __syncthreads();
    float s = 0.f;
    for (int i = tid; i < len; i += 128) { float e = expf(row[i] - mx); row[i] = e; s += e; }
    red[tid] = s; __syncthreads();
    for (int o = 64; o > 0; o >>= 1) {
        if (tid < o) red[tid] += red[tid + o];
        __syncthreads();
    }
    float inv = 1.0f / red[0];
    __nv_bfloat16 z0 = __float2bfloat16(0.f);
    for (int i = tid; i < len; i += 128)
        store_split(row[i] * inv, PH + base + i, PL + base + i);
    for (int i = len + tid; i < NT; i += 128) { PH[base + i] = z0; PL[base + i] = z0; }
}

// ---------------- router logits + softmax over experts -----------------------
__global__ void router_kernel(const float* __restrict__ xn, const float* __restrict__ wr,
                              float* __restrict__ probs) {
    int n = blockIdx.x;
    const float* xr = xn + (long long)n * ND;
    float acc[NE];
#pragma unroll
    for (int e = 0; e < NE; e++) acc[e] = 0.f;
    for (int d = threadIdx.x; d < ND; d += 128) {
        float xv = xr[d];
#pragma unroll
        for (int e = 0; e < NE; e++) acc[e] += xv * wr[e * ND + d];
    }
    __shared__ float red[128];
    __shared__ float logit[NE];
    for (int e = 0; e < NE; e++) {
        red[threadIdx.x] = acc[e]; __syncthreads();
        for (int o = 64; o > 0; o >>= 1) {
            if (threadIdx.x < o) red[threadIdx.x] += red[threadIdx.x + o];
            __syncthreads();
        }
        if (threadIdx.x == 0) logit[e] = red[0];
        __syncthreads();
    }
    if (threadIdx.x == 0) {
        float mx = logit[0];
        for (int e = 1; e < NE; e++) mx = fmaxf(mx, logit[e]);
        float s = 0.f; float ex[NE];
        for (int e = 0; e < NE; e++) { ex[e] = expf(logit[e] - mx); s += ex[e]; }
        float inv = 1.0f / s;
        for (int e = 0; e < NE; e++) probs[(long long)n * NE + e] = ex[e] * inv;
    }
}

// ---------------- per-expert top-k via in-smem bitonic sort -------------------
__global__ void topk_kernel(const float* __restrict__ probs, int* __restrict__ sel,
                            float* __restrict__ weights) {
    int e = blockIdx.x;
    __shared__ float v[NTOK];
    __shared__ int ix[NTOK];
    int tid = threadIdx.x;
    for (int i = tid; i < NTOK; i += 1024) { v[i] = probs[(long long)i * NE + e]; ix[i] = i; }
    __syncthreads();
    for (int k = 2; k <= NTOK; k <<= 1) {
        for (int j = k >> 1; j > 0; j >>= 1) {
            for (int i = tid; i < NTOK; i += 1024) {
                int p = i ^ j;
                if (p > i) {
                    float va = v[i], vb = v[p];
                    int ia = ix[i], ib = ix[p];
                    bool sw;
                    if ((i & k) == 0) sw = (vb > va) || (vb == va && ib < ia);
                    else              sw = (va > vb) || (va == vb && ia < ib);
                    if (sw) { v[i] = vb; v[p] = va; ix[i] = ib; ix[p] = ia; }
                }
            }
            __syncthreads();
        }
    }
    for (int i = tid; i < NTOPK; i += 1024) {
        sel[e * NTOPK + i] = ix[i];
        weights[e * NTOPK + i] = v[i];
    }
}

// ---------------- LM head: logits for last token of each batch ----------------
__global__ void lmhead_kernel(const float* __restrict__ xf, const float* __restrict__ wte,
                              float* __restrict__ out) {
    __shared__ float xs[NB * ND];
    for (int i = threadIdx.x; i < NB * ND; i += 256) xs[i] = xf[i];
    __syncthreads();
    int warp = threadIdx.x >> 5, lane = threadIdx.x & 31;
    int vtok = blockIdx.x * 8 + warp;
    if (vtok < NV) {
        const float* wrow = wte + (long long)vtok * ND;
        float a0 = 0.f, a1 = 0.f, a2 = 0.f, a3 = 0.f;
        for (int d = lane; d < ND; d += 32) {
            float w = wrow[d];
            a0 += w * xs[d];
            a1 += w * xs[ND + d];
            a2 += w * xs[2 * ND + d];
            a3 += w * xs[3 * ND + d];
        }
#pragma unroll
        for (int o = 16; o > 0; o >>= 1) {
            a0 += __shfl_down_sync(0xffffffffu, a0, o);
            a1 += __shfl_down_sync(0xffffffffu, a1, o);
            a2 += __shfl_down_sync(0xffffffffu, a2, o);
            a3 += __shfl_down_sync(0xffffffffu, a3, o);
        }
        if (lane == 0) {
            out[0 * NV + vtok] = a0;
            out[1 * NV + vtok] = a1;
            out[2 * NV + vtok] = a2;
            out[3 * NV + vtok] = a3;
        }
    }
}

// ---------------- host-side orchestration ------------------------------------
static float* SYM_F(const void* s) { void* p; cudaGetSymbolAddress(&p, s); return (float*)p; }

extern "C" void kernel_launch(void* const* d_in, const int* in_sizes, int n_in,
                              void* d_out, int out_size) {
    (void)in_sizes; (void)n_in; (void)out_size;
    const int*   idx         = (const int*)d_in[0];
    const float* wte         = (const float*)d_in[1];
    const float* wpe         = (const float*)d_in[2];
    const float* ln1_w       = (const float*)d_in[3];
    const float* attn_w      = (const float*)d_in[4];
    const float* attn_proj_w = (const float*)d_in[5];
    const float* ln2_w       = (const float*)d_in[6];
    const float* router_w    = (const float*)d_in[7];
    const float* fc_w        = (const float*)d_in[8];
    const float* proj_w      = (const float*)d_in[9];
    const float* lnf_w       = (const float*)d_in[10];
    float* out = (float*)d_out;

    void* p;
#define GET(sym, T, name) cudaGetSymbolAddress(&p, sym); T* name = (T*)p
    GET(g_x, float, x);
    GET(g_xn, float, xn);
    GET(g_S, float, S);
    GET(g_probs, float, probs);
    GET(g_wsel, float, wsel);
    GET(g_sel, int, sel);
    GET(g_xf, float, xf);
    GET(g_xnH, __nv_bfloat16, xnH);   GET(g_xnL, __nv_bfloat16, xnL);
    GET(g_qkvH, __nv_bfloat16, qkvH); GET(g_qkvL, __nv_bfloat16, qkvL);
    GET(g_VtH, __nv_bfloat16, VtH);   GET(g_VtL, __nv_bfloat16, VtL);
    GET(g_PH, __nv_bfloat16, PH);     GET(g_PL, __nv_bfloat16, PL);
    GET(g_attH, __nv_bfloat16, attH); GET(g_attL, __nv_bfloat16, attL);
    GET(g_hH, __nv_bfloat16, hH);     GET(g_hL, __nv_bfloat16, hL);
    GET(g_awH, __nv_bfloat16, awH);   GET(g_awL, __nv_bfloat16, awL);
    GET(g_apwH, __nv_bfloat16, apwH); GET(g_apwL, __nv_bfloat16, apwL);
    GET(g_fwH, __nv_bfloat16, fwH);   GET(g_fwL, __nv_bfloat16, fwL);
    GET(g_pjwH, __nv_bfloat16, pjwH); GET(g_pjwL, __nv_bfloat16, pjwL);
#undef GET

    cudaFuncSetAttribute(gemm_kernel, cudaFuncAttributeMaxDynamicSharedMemorySize, SMEM_BYTES);

    // one-time (per launch) weight splits
    {
        int n;
        n = NL * 3 * ND * ND;
        split_kernel<<<(n / 4 + 255) / 256, 256>>>(attn_w, awH, awL, n / 4);
        n = NL * ND * ND;
        split_kernel<<<(n / 4 + 255) / 256, 256>>>(attn_proj_w, apwH, apwL, n / 4);
        n = NL * NE * NDFF * ND;
        split_kernel<<<(n / 4 + 255) / 256, 256>>>(fc_w, fwH, fwL, n / 4);
        split_kernel<<<(n / 4 + 255) / 256, 256>>>(proj_w, pjwH, pjwL, n / 4);
    }

    embed_kernel<<<NTOK, 256>>>(idx, wte, wpe, x);

    for (int l = 0; l < NL; l++) {
        const float* ln1 = ln1_w + l * ND;
        const float* ln2 = ln2_w + l * ND;
        const float* rw  = router_w + (long long)l * NE * ND;
        __nv_bfloat16* lawH = awH + (long long)l * 3 * ND * ND;
        __nv_bfloat16* lawL = awL + (long long)l * 3 * ND * ND;
        __nv_bfloat16* lapH = apwH + (long long)l * ND * ND;
        __nv_bfloat16* lapL = apwL + (long long)l * ND * ND;
        __nv_bfloat16* lfwH = fwH + (long long)l * NE * NDFF * ND;
        __nv_bfloat16* lfwL = fwL + (long long)l * NE * NDFF * ND;
        __nv_bfloat16* lpjH = pjwH + (long long)l * NE * ND * NDFF;
        __nv_bfloat16* lpjL = pjwL + (long long)l * NE * ND * NDFF;

        // ---- attention ----
        rmsnorm_kernel<<<NTOK, 256>>>(x, ln1, nullptr, xnH, xnL, 1, 0);
        // qkv (epilogue 3: Q,K -> split qkv; V -> transposed Vt)
        gemm_kernel<<<dim3(3 * ND / BN, NTOK / BM, 1), 256, SMEM_BYTES>>>(
            xnH, xnL, lawH, lawL, nullptr, qkvH, qkvL, VtH, VtL,
            NTOK, 3 * ND, ND, ND, ND, 3 * ND,
            0, 0, 0, 0, 0, 0, 1, 1.0f,
            nullptr, nullptr, 3, nullptr, nullptr, nullptr);
        // S = (Q K^T)/8 per (b,h): fp32
        gemm_kernel<<<dim3(NT / BN, NT / BM, NB * NH), 256, SMEM_BYTES>>>(
            qkvH, qkvL, qkvH + ND, qkvL + ND, S, nullptr, nullptr, nullptr, nullptr,
            NT, NT, NHD, 3 * ND, 3 * ND, NT,
            (long long)NT * 3 * ND, NHD, (long long)NT * 3 * ND, NHD,
            (long long)NH * NT * NT, (long long)NT * NT, NH, 0.125f,
            nullptr, nullptr, 0, nullptr, nullptr, nullptr);
        softmax_kernel<<<dim3(NT, NB * NH), 128>>>(S, PH, PL);
        // att = P Vt^T per (b,h) -> split att (epilogue 4)
        gemm_kernel<<<dim3(1, NT / BM, NB * NH), 256, SMEM_BYTES>>>(
            PH, PL, VtH, VtL, nullptr, attH, attL, nullptr, nullptr,
            NT, NHD, NT, NT, NT, ND,
            (long long)NH * NT * NT, (long long)NT * NT,
            (long long)NH * NHD * NT, (long long)NHD * NT,
            (long long)NT * ND, NHD, NH, 1.0f,
            nullptr, nullptr, 4, nullptr, nullptr, nullptr);
        // x = x + att @ attn_proj^T (fp32)
        gemm_kernel<<<dim3(ND / BN, NTOK / BM, 1), 256, SMEM_BYTES>>>(
            attH, attL, lapH, lapL, x, nullptr, nullptr, nullptr, nullptr,
            NTOK, ND, ND, ND, ND, ND,
            0, 0, 0, 0, 0, 0, 1, 1.0f,
            x, nullptr, 0, nullptr, nullptr, nullptr);

        // ---- MoE ----
        rmsnorm_kernel<<<NTOK, 256>>>(x, ln2, xn, xnH, xnL, 1, 0);
        router_kernel<<<NTOK, 128>>>(xn, rw, probs);
        topk_kernel<<<NE, 1024>>>(probs, sel, wsel);
        // h[e] = gelu( xn[sel[e]] @ fc_w[e]^T ) -> split h (epilogue 1)
        gemm_kernel<<<dim3(NDFF / BN, NTOPK / BM, NE), 256, SMEM_BYTES>>>(
            xnH, xnL, lfwH, lfwL, nullptr, hH, hL, nullptr, nullptr,
            NTOPK, NDFF, ND, ND, ND, NDFF,
            0, 0, (long long)NDFF * ND, 0, (long long)NTOPK * NDFF, 0, 1, 1.0f,
            nullptr, sel, 1, nullptr, nullptr, nullptr);
        // x[sel[e,k]] += w[e,k] * (h[e] @ proj_w[e]^T)   (epilogue 2)
        gemm_kernel<<<dim3(ND / BN, NTOPK / BM, NE), 256, SMEM_BYTES>>>(
            hH, hL, lpjH, lpjL, nullptr, nullptr, nullptr, nullptr, nullptr,
            NTOPK, ND, NDFF, NDFF, NDFF, ND,
            (long long)NTOPK * NDFF, 0, (long long)ND * NDFF, 0, 0, 0, 1, 1.0f,
            nullptr, nullptr, 2, sel, wsel, x);
    }

    rmsnorm_kernel<<<NB, 256>>>(x, lnf_w, xf, nullptr, nullptr, NT, NT - 1);
    lmhead_kernel<<<(NV + 7) / 8, 256>>>(xf, wte, out);
}

// round 11
// speedup vs baseline: 3.1708x; 1.0843x over previous
#include <cuda_runtime.h>
#include <cuda_bf16.h>
#include <math.h>
#include <stdint.h>

#define NB 4
#define NT 1024
#define ND 1024
#define NH 16
#define NL 2
#define NE 8
#define NDFF 4096
#define NV 50257
#define NHD 64
#define NTOK 4096   // NB*NT
#define NTOPK 1024  // CAP*NB*NT/NE

// ---------------- scratch (static device allocations; no cudaMalloc) ----------
__device__ float g_x[NTOK * ND];
__device__ float g_xn[NTOK * ND];           // fp32 xn (router input)
__device__ float g_S[(size_t)NB * NH * NT * NT];
__device__ float g_probs[NTOK * NE];
__device__ float g_wsel[NE * NTOPK];
__device__ int   g_sel[NE * NTOPK];
__device__ float g_xf[NB * ND];

// split bf16 activations
__device__ __nv_bfloat16 g_xnH[NTOK * ND],  g_xnL[NTOK * ND];
__device__ __nv_bfloat16 g_qkvH[NTOK * 3 * ND], g_qkvL[NTOK * 3 * ND];  // V region unused
__device__ __nv_bfloat16 g_VtH[(NB * NH * NHD + 128) * NT], g_VtL[(NB * NH * NHD + 128) * NT];
__device__ __nv_bfloat16 g_PH[(size_t)NB * NH * NT * NT], g_PL[(size_t)NB * NH * NT * NT];
__device__ __nv_bfloat16 g_attH[NTOK * ND], g_attL[NTOK * ND];
__device__ __nv_bfloat16 g_hH[(size_t)NE * NTOPK * NDFF], g_hL[(size_t)NE * NTOPK * NDFF];

// split bf16 weights
__device__ __nv_bfloat16 g_awH[NL * 3 * ND * ND],  g_awL[NL * 3 * ND * ND];
__device__ __nv_bfloat16 g_apwH[NL * ND * ND],     g_apwL[NL * ND * ND];
__device__ __nv_bfloat16 g_fwH[(size_t)NL * NE * NDFF * ND], g_fwL[(size_t)NL * NE * NDFF * ND];
__device__ __nv_bfloat16 g_pjwH[(size_t)NL * NE * ND * NDFF], g_pjwL[(size_t)NL * NE * ND * NDFF];

// ---------------- helpers ------------------------------------------------------
__device__ __forceinline__ void store_split(float v, __nv_bfloat16* ph, __nv_bfloat16* pl) {
    __nv_bfloat16 h = __float2bfloat16(v);
    *ph = h;
    *pl = __float2bfloat16(v - __bfloat162float(h));
}

__device__ __forceinline__ void split2(float x, float y, uint32_t& h, uint32_t& l) {
    __nv_bfloat16 hx = __float2bfloat16(x), hy = __float2bfloat16(y);
    __nv_bfloat16 lx = __float2bfloat16(x - __bfloat162float(hx));
    __nv_bfloat16 ly = __float2bfloat16(y - __bfloat162float(hy));
    uint16_t uhx = *(uint16_t*)&hx, uhy = *(uint16_t*)&hy;
    uint16_t ulx = *(uint16_t*)&lx, uly = *(uint16_t*)&ly;
    h = ((uint32_t)uhy << 16) | uhx;
    l = ((uint32_t)uly << 16) | ulx;
}

__device__ __forceinline__ uint32_t smem_u32(const void* p) {
    return (uint32_t)__cvta_generic_to_shared(p);
}

__device__ __forceinline__ void cp16(void* dst_smem, const void* src) {
    asm volatile("cp.async.cg.shared.global [%0], [%1], 16;"
                 :: "r"(smem_u32(dst_smem)), "l"(src));
}
#define CP_COMMIT() asm volatile("cp.async.commit_group;")
#define CP_WAIT0()  asm volatile("cp.async.wait_group 0;")

__device__ __forceinline__ void mma_bf16(float* c, const uint32_t* a,
                                         uint32_t b0, uint32_t b1) {
    asm volatile(
        "mma.sync.aligned.m16n8k16.row.col.f32.bf16.bf16.f32 "
        "{%0,%1,%2,%3}, {%4,%5,%6,%7}, {%8,%9}, {%0,%1,%2,%3};"
        : "+f"(c[0]), "+f"(c[1]), "+f"(c[2]), "+f"(c[3])
        : "r"(a[0]), "r"(a[1]), "r"(a[2]), "r"(a[3]), "r"(b0), "r"(b1));
}

__device__ __forceinline__ void ldsm_x4(uint32_t* r, uint32_t addr) {
    asm volatile("ldmatrix.sync.aligned.m8n8.x4.shared.b16 {%0,%1,%2,%3}, [%4];"
                 : "=r"(r[0]), "=r"(r[1]), "=r"(r[2]), "=r"(r[3]) : "r"(addr));
}

// ---------------- fp32 -> (hi, lo) bf16 conversion (packed stores) ------------
__global__ void split_kernel(const float4* __restrict__ src, uint2* __restrict__ h2,
                             uint2* __restrict__ l2, int n4) {
    int i = blockIdx.x * blockDim.x + threadIdx.x;
    if (i < n4) {
        float4 v = src[i];
        uint32_t h0, l0, h1, l1;
        split2(v.x, v.y, h0, l0);
        split2(v.z, v.w, h1, l1);
        h2[i] = make_uint2(h0, h1);
        l2[i] = make_uint2(l0, l1);
    }
}

// ---------------- embedding ---------------------------------------------------
__global__ void embed_kernel(const int* __restrict__ idx, const float* __restrict__ wte,
                             const float* __restrict__ wpe, float* __restrict__ x) {
    int n = blockIdx.x;
    int t = n & (NT - 1);
    long long r = idx[n];
    const float* a = wte + r * ND;
    const float* b = wpe + (long long)t * ND;
    float* o = x + (long long)n * ND;
    for (int d = threadIdx.x; d < ND; d += blockDim.x) o[d] = a[d] + b[d];
}

// ---------------- rmsnorm (fp32 and/or split-bf16 output) ---------------------
__global__ void rmsnorm_kernel(const float* __restrict__ x, const float* __restrict__ w,
                               float* __restrict__ outF,
                               __nv_bfloat16* __restrict__ outH,
                               __nv_bfloat16* __restrict__ outL,
                               int rowMul, int rowAdd) {
    int orow = blockIdx.x;
    long long irow = (long long)orow * rowMul + rowAdd;
    const float* xr = x + irow * ND;
    __shared__ float red[256];
    float s = 0.f;
    for (int d = threadIdx.x; d < ND; d += 256) { float v = xr[d]; s += v * v; }
    red[threadIdx.x] = s; __syncthreads();
    for (int o = 128; o > 0; o >>= 1) {
        if (threadIdx.x < o) red[threadIdx.x] += red[threadIdx.x + o];
        __syncthreads();
    }
    float scale = 1.0f / sqrtf(red[0] * (1.0f / ND) + 1e-6f);
    long long ob = (long long)orow * ND;
    for (int d = threadIdx.x; d < ND; d += 256) {
        float v = xr[d] * scale * w[d];
        if (outF) outF[ob + d] = v;
        if (outH) store_split(v, outH + ob + d, outL + ob + d);
    }
}

// ---------------- tensor-core batched GEMM (pre-split bf16 operands) ----------
// C = alpha * A @ B^T with A=[M,K] via (AH,AL), B=[N,K] via (BH,BL), both row-major.
// 3-term split product: Ah*Bh + Ah*Bl + Al*Bh. cp.async double-buffered.
// epilogue: 0 fp32 store (+residual), 1 GELU->split, 2 scaled atomic scatter,
//           3 qkv special (Q,K split store; V -> transposed Vt split store),
//           4 plain split store.
// causal: bit0 -> skip tiles with n0 > m0+BM-1 (score GEMM)
//         bit1 -> clamp K to m0+BM (PV GEMM)
#define BM 128
#define BN 128
#define BK 32
#define LDS_PAD 40
#define MT (BM * LDS_PAD)
#define ST (4 * MT)
#define SMEM_BYTES (2 * ST * 2)

__global__ __launch_bounds__(256, 2) void gemm_kernel(
    const __nv_bfloat16* __restrict__ AH, const __nv_bfloat16* __restrict__ AL,
    const __nv_bfloat16* __restrict__ BH, const __nv_bfloat16* __restrict__ BL,
    float* __restrict__ C, __nv_bfloat16* __restrict__ CH, __nv_bfloat16* __restrict__ CL,
    __nv_bfloat16* __restrict__ VtH, __nv_bfloat16* __restrict__ VtL,
    int M, int N, int K, int lda, int ldb, int ldc,
    long long sA1, long long sA2, long long sB1, long long sB2,
    long long sC1, long long sC2, int zdiv, float alpha,
    const float* __restrict__ residual, const int* __restrict__ rowsA,
    int epilogue, const int* __restrict__ rowsOut,
    const float* __restrict__ rowScale, float* __restrict__ scatter, int causal)
{
    extern __shared__ __nv_bfloat16 sm[];

    int m0 = blockIdx.y * BM, n0 = blockIdx.x * BN;
    if ((causal & 1) && n0 > m0 + BM - 1) return;   // fully-masked score tile

    int z = blockIdx.z;
    int z1 = z / zdiv, z2 = z - z1 * zdiv;
    long long offA = z1 * sA1 + z2 * sA2;
    long long offB = z1 * sB1 + z2 * sB2;
    long long offC = z1 * sC1 + z2 * sC2;
    AH += offA; AL += offA;
    BH += offB; BL += offB;
    if (C)  C  += offC;
    if (CH) { CH += offC; CL += offC; }

    int tid = threadIdx.x;
    int lane = tid & 31;
    int warpId = tid >> 5;
    int wm = (warpId & 3) * 32;
    int wn = (warpId >> 2) * 64;

    float acc[2][8][4];
#pragma unroll
    for (int mi = 0; mi < 2; mi++)
#pragma unroll
        for (int ni = 0; ni < 8; ni++)
#pragma unroll
            for (int t = 0; t < 4; t++) acc[mi][ni][t] = 0.f;

    int am = tid >> 1, ac = (tid & 1) * 16;
    long long arow = m0 + am;
    if (rowsA) arow = rowsA[(long long)z * M + m0 + am];
    const __nv_bfloat16* gAH = AH + arow * (long long)lda + ac;
    const __nv_bfloat16* gAL = AL + arow * (long long)lda + ac;
    const __nv_bfloat16* gBH = BH + (long long)(n0 + am) * ldb + ac;
    const __nv_bfloat16* gBL = BL + (long long)(n0 + am) * ldb + ac;
    int dstA = am * LDS_PAD + ac;

    int Klim = (causal & 2) ? (m0 + BM < K ? m0 + BM : K) : K;
    int nTiles = Klim / BK;

    {
        __nv_bfloat16* s = sm;
        cp16(s + dstA,               gAH);
        cp16(s + dstA + 8,           gAH + 8);
        cp16(s + MT + dstA,          gAL);
        cp16(s + MT + dstA + 8,      gAL + 8);
        cp16(s + 2 * MT + dstA,      gBH);
        cp16(s + 2 * MT + dstA + 8,  gBH + 8);
        cp16(s + 3 * MT + dstA,      gBL);
        cp16(s + 3 * MT + dstA + 8,  gBL + 8);
        CP_COMMIT();
    }

    int arl = lane & 15;
    int acl = (lane >> 4) * 8;
    int brl = (lane & 7) + ((lane & 16) >> 1);

    for (int it = 0; it < nTiles; it++) {
        CP_WAIT0();
        __syncthreads();

        if (it + 1 < nTiles) {
            int k0 = (it + 1) * BK;
            __nv_bfloat16* s = sm + ((it + 1) & 1) * ST;
            cp16(s + dstA,               gAH + k0);
            cp16(s + dstA + 8,           gAH + k0 + 8);
            cp16(s + MT + dstA,          gAL + k0);
            cp16(s + MT + dstA + 8,      gAL + k0 + 8);
            cp16(s + 2 * MT + dstA,      gBH + k0);
            cp16(s + 2 * MT + dstA + 8,  gBH + k0 + 8);
            cp16(s + 3 * MT + dstA,      gBL + k0);
            cp16(s + 3 * MT + dstA + 8,  gBL + k0 + 8);
            CP_COMMIT();
        }

        const __nv_bfloat16* pAH = sm + (it & 1) * ST;
        const __nv_bfloat16* pAL = pAH + MT;
        const __nv_bfloat16* pBH = pAH + 2 * MT;
        const __nv_bfloat16* pBL = pAH + 3 * MT;

#pragma unroll
        for (int ks = 0; ks < 2; ks++) {
            int kk = ks * 16;
            uint32_t ah[2][4], al[2][4];
#pragma unroll
            for (int mi = 0; mi < 2; mi++) {
                int r0 = wm + mi * 16 + arl;
                ldsm_x4(ah[mi], smem_u32(pAH + r0 * LDS_PAD + kk + acl));
                ldsm_x4(al[mi], smem_u32(pAL + r0 * LDS_PAD + kk + acl));
            }
            int bcl = kk + (lane & 8);
#pragma unroll
            for (int nip = 0; nip < 4; nip++) {
                int cn = wn + nip * 16 + brl;
                uint32_t bh[4], bl[4];
                ldsm_x4(bh, smem_u32(pBH + cn * LDS_PAD + bcl));
                ldsm_x4(bl, smem_u32(pBL + cn * LDS_PAD + bcl));
#pragma unroll
                for (int mi = 0; mi < 2; mi++) {
                    mma_bf16(acc[mi][2 * nip], ah[mi], bh[0], bh[1]);
                    mma_bf16(acc[mi][2 * nip], ah[mi], bl[0], bl[1]);
                    mma_bf16(acc[mi][2 * nip], al[mi], bh[0], bh[1]);
                    mma_bf16(acc[mi][2 * nip + 1], ah[mi], bh[2], bh[3]);
                    mma_bf16(acc[mi][2 * nip + 1], ah[mi], bl[2], bl[3]);
                    mma_bf16(acc[mi][2 * nip + 1], al[mi], bh[2], bh[3]);
                }
            }
        }
        __syncthreads();
    }

    int fr = lane >> 2;
    int fc = (lane & 3) * 2;
#pragma unroll
    for (int mi = 0; mi < 2; mi++) {
#pragma unroll
        for (int ni = 0; ni < 8; ni++) {
            int mBase = m0 + wm + mi * 16 + fr;
            int nBase = n0 + wn + ni * 8 + fc;
#pragma unroll
            for (int half = 0; half < 2; half++) {
                int m = mBase + half * 8;
                if (m >= M) continue;
#pragma unroll
                for (int t = 0; t < 2; t++) {
                    int n = nBase + t;
                    if (n >= N) continue;
                    float v = acc[mi][ni][half * 2 + t] * alpha;
                    long long ci = (long long)m * ldc + n;
                    if (epilogue == 0) {
                        if (residual) v += residual[ci];
                        C[ci] = v;
                    } else if (epilogue == 1) {
                        v = 0.5f * v * (1.0f + erff(v * 0.70710678118654752440f));
                        store_split(v, CH + ci, CL + ci);
                    } else if (epilogue == 2) {
                        long long rr = rowsOut[(long long)z * M + m];
                        atomicAdd(&scatter[rr * ldc + n],
                                  rowScale[(long long)z * M + m] * v);
                    } else if (epilogue == 3) {
                        if (n < 2 * ND) {
                            store_split(v, CH + ci, CL + ci);
                        } else {
                            int b = m >> 10, tt = m & (NT - 1);
                            int c = n - 2 * ND;
                            int h = c >> 6, d = c & (NHD - 1);
                            long long vi = ((long long)((b * NH + h) * NHD + d)) * NT + tt;
                            store_split(v, VtH + vi, VtL + vi);
                        }
                    } else {
                        store_split(v, CH + ci, CL + ci);
                    }
                }
            }
        }
    }
}

// ---------------- causal softmax: fp32 S row -> split-bf16 P row --------------
__global__ void softmax_kernel(float* __restrict__ S, __nv_bfloat16* __restrict__ PH,
                               __nv_bfloat16* __restrict__ PL) {
    int q = blockIdx.x;
    long long z = blockIdx.y;
    long long base = z * (long long)NT * NT + (long long)q * NT;
    float* row = S + base;
    int len = q + 1;
    __shared__ float red[128];
    int tid = threadIdx.x;
    float mx = -1e30f;
    for (int i = tid; i < len; i += 128) mx = fmaxf(mx, row[i]);
    red[tid] = mx; __syncthreads();
    for (int o = 64; o > 0; o >>= 1) {
        if (tid < o) red[tid] = fmaxf(red[tid], red[tid + o]);
        __syncthreads();
    }
    mx = red[0]; __syncthreads();
    float s = 0.f;
    for (int i = tid; i < len; i += 128) { float e = expf(row[i] - mx); row[i] = e; s += e; }
    red[tid] = s; __syncthreads();
    for (int o = 64; o > 0; o >>= 1) {
        if (tid < o) red[tid] += red[tid + o];
        __syncthreads();
    }
    float inv = 1.0f / red[0];
    __nv_bfloat16 z0 = __float2bfloat16(0.f);
    for (int i = tid; i < len; i += 128)
        store_split(row[i] * inv, PH + base + i, PL + base + i);
    int zend = ((q >> 7) + 1) << 7;   // clamped PV reads only up to next 128 boundary
    for (int i = len + tid; i < zend; i += 128) { PH[base + i] = z0; PL[base + i] = z0; }
}

// ---------------- router logits + softmax over experts -----------------------
__global__ void router_kernel(const float* __restrict__ xn, const float* __restrict__ wr,
                              float* __restrict__ probs) {
    int n = blockIdx.x;
    const float* xr = xn + (long long)n * ND;
    float acc[NE];
#pragma unroll
    for (int e = 0; e < NE; e++) acc[e] = 0.f;
    for (int d = threadIdx.x; d < ND; d += 128) {
        float xv = xr[d];
#pragma unroll
        for (int e = 0; e < NE; e++) acc[e] += xv * wr[e * ND + d];
    }
    __shared__ float red[128];
    __shared__ float logit[NE];
    for (int e = 0; e < NE; e++) {
        red[threadIdx.x] = acc[e]; __syncthreads();
        for (int o = 64; o > 0; o >>= 1) {
            if (threadIdx.x < o) red[threadIdx.x] += red[threadIdx.x + o];
            __syncthreads();
        }
        if (threadIdx.x == 0) logit[e] = red[0];
        __syncthreads();
    }
    if (threadIdx.x == 0) {
        float mx = logit[0];
        for (int e = 1; e < NE; e++) mx = fmaxf(mx, logit[e]);
        float s = 0.f; float ex[NE];
        for (int e = 0; e < NE; e++) { ex[e] = expf(logit[e] - mx); s += ex[e]; }
        float inv = 1.0f / s;
        for (int e = 0; e < NE; e++) probs[(long long)n * NE + e] = ex[e] * inv;
    }
}

// ---------------- per-expert top-k via in-smem bitonic sort -------------------
__global__ void topk_kernel(const float* __restrict__ probs, int* __restrict__ sel,
                            float* __restrict__ weights) {
    int e = blockIdx.x;
    __shared__ float v[NTOK];
    __shared__ int ix[NTOK];
    int tid = threadIdx.x;
    for (int i = tid; i < NTOK; i += 1024) { v[i] = probs[(long long)i * NE + e]; ix[i] = i; }
    __syncthreads();
    for (int k = 2; k <= NTOK; k <<= 1) {
        for (int j = k >> 1; j > 0; j >>= 1) {
            for (int i = tid; i < NTOK; i += 1024) {
                int p = i ^ j;
                if (p > i) {
                    float va = v[i], vb = v[p];
                    int ia = ix[i], ib = ix[p];
                    bool sw;
                    if ((i & k) == 0) sw = (vb > va) || (vb == va && ib < ia);
                    else              sw = (va > vb) || (va == vb && ia < ib);
                    if (sw) { v[i] = vb; v[p] = va; ix[i] = ib; ix[p] = ia; }
                }
            }
            __syncthreads();
        }
    }
    for (int i = tid; i < NTOPK; i += 1024) {
        sel[e * NTOPK + i] = ix[i];
        weights[e * NTOPK + i] = v[i];
    }
}

// ---------------- LM head: logits for last token of each batch ----------------
__global__ void lmhead_kernel(const float* __restrict__ xf, const float* __restrict__ wte,
                              float* __restrict__ out) {
    __shared__ float xs[NB * ND];
    for (int i = threadIdx.x; i < NB * ND; i += 256) xs[i] = xf[i];
    __syncthreads();
    int warp = threadIdx.x >> 5, lane = threadIdx.x & 31;
    int vtok = blockIdx.x * 8 + warp;
    if (vtok < NV) {
        const float* wrow = wte + (long long)vtok * ND;
        float a0 = 0.f, a1 = 0.f, a2 = 0.f, a3 = 0.f;
        for (int d = lane; d < ND; d += 32) {
            float w = wrow[d];
            a0 += w * xs[d];
            a1 += w * xs[ND + d];
            a2 += w * xs[2 * ND + d];
            a3 += w * xs[3 * ND + d];
        }
#pragma unroll
        for (int o = 16; o > 0; o >>= 1) {
            a0 += __shfl_down_sync(0xffffffffu, a0, o);
            a1 += __shfl_down_sync(0xffffffffu, a1, o);
            a2 += __shfl_down_sync(0xffffffffu, a2, o);
            a3 += __shfl_down_sync(0xffffffffu, a3, o);
        }
        if (lane == 0) {
            out[0 * NV + vtok] = a0;
            out[1 * NV + vtok] = a1;
            out[2 * NV + vtok] = a2;
            out[3 * NV + vtok] = a3;
        }
    }
}

// ---------------- host-side orchestration ------------------------------------
extern "C" void kernel_launch(void* const* d_in, const int* in_sizes, int n_in,
                              void* d_out, int out_size) {
    (void)in_sizes; (void)n_in; (void)out_size;
    const int*   idx         = (const int*)d_in[0];
    const float* wte         = (const float*)d_in[1];
    const float* wpe         = (const float*)d_in[2];
    const float* ln1_w       = (const float*)d_in[3];
    const float* attn_w      = (const float*)d_in[4];
    const float* attn_proj_w = (const float*)d_in[5];
    const float* ln2_w       = (const float*)d_in[6];
    const float* router_w    = (const float*)d_in[7];
    const float* fc_w        = (const float*)d_in[8];
    const float* proj_w      = (const float*)d_in[9];
    const float* lnf_w       = (const float*)d_in[10];
    float* out = (float*)d_out;

    void* p;
#define GET(sym, T, name) cudaGetSymbolAddress(&p, sym); T* name = (T*)p
    GET(g_x, float, x);
    GET(g_xn, float, xn);
    GET(g_S, float, S);
    GET(g_probs, float, probs);
    GET(g_wsel, float, wsel);
    GET(g_sel, int, sel);
    GET(g_xf, float, xf);
    GET(g_xnH, __nv_bfloat16, xnH);   GET(g_xnL, __nv_bfloat16, xnL);
    GET(g_qkvH, __nv_bfloat16, qkvH); GET(g_qkvL, __nv_bfloat16, qkvL);
    GET(g_VtH, __nv_bfloat16, VtH);   GET(g_VtL, __nv_bfloat16, VtL);
    GET(g_PH, __nv_bfloat16, PH);     GET(g_PL, __nv_bfloat16, PL);
    GET(g_attH, __nv_bfloat16, attH); GET(g_attL, __nv_bfloat16, attL);
    GET(g_hH, __nv_bfloat16, hH);     GET(g_hL, __nv_bfloat16, hL);
    GET(g_awH, __nv_bfloat16, awH);   GET(g_awL, __nv_bfloat16, awL);
    GET(g_apwH, __nv_bfloat16, apwH); GET(g_apwL, __nv_bfloat16, apwL);
    GET(g_fwH, __nv_bfloat16, fwH);   GET(g_fwL, __nv_bfloat16, fwL);
    GET(g_pjwH, __nv_bfloat16, pjwH); GET(g_pjwL, __nv_bfloat16, pjwL);
#undef GET

    cudaFuncSetAttribute(gemm_kernel, cudaFuncAttributeMaxDynamicSharedMemorySize, SMEM_BYTES);

    {
        int n;
        n = NL * 3 * ND * ND;
        split_kernel<<<(n / 4 + 255) / 256, 256>>>((const float4*)attn_w, (uint2*)awH, (uint2*)awL, n / 4);
        n = NL * ND * ND;
        split_kernel<<<(n / 4 + 255) / 256, 256>>>((const float4*)attn_proj_w, (uint2*)apwH, (uint2*)apwL, n / 4);
        n = NL * NE * NDFF * ND;
        split_kernel<<<(n / 4 + 255) / 256, 256>>>((const float4*)fc_w, (uint2*)fwH, (uint2*)fwL, n / 4);
        split_kernel<<<(n / 4 + 255) / 256, 256>>>((const float4*)proj_w, (uint2*)pjwH, (uint2*)pjwL, n / 4);
    }

    embed_kernel<<<NTOK, 256>>>(idx, wte, wpe, x);

    for (int l = 0; l < NL; l++) {
        const float* ln1 = ln1_w + l * ND;
        const float* ln2 = ln2_w + l * ND;
        const float* rw  = router_w + (long long)l * NE * ND;
        __nv_bfloat16* lawH = awH + (long long)l * 3 * ND * ND;
        __nv_bfloat16* lawL = awL + (long long)l * 3 * ND * ND;
        __nv_bfloat16* lapH = apwH + (long long)l * ND * ND;
        __nv_bfloat16* lapL = apwL + (long long)l * ND * ND;
        __nv_bfloat16* lfwH = fwH + (long long)l * NE * NDFF * ND;
        __nv_bfloat16* lfwL = fwL + (long long)l * NE * NDFF * ND;
        __nv_bfloat16* lpjH = pjwH + (long long)l * NE * ND * NDFF;
        __nv_bfloat16* lpjL = pjwL + (long long)l * NE * ND * NDFF;

        // ---- attention ----
        rmsnorm_kernel<<<NTOK, 256>>>(x, ln1, nullptr, xnH, xnL, 1, 0);
        // qkv (epilogue 3: Q,K -> split qkv; V -> transposed Vt)
        gemm_kernel<<<dim3(3 * ND / BN, NTOK / BM, 1), 256, SMEM_BYTES>>>(
            xnH, xnL, lawH, lawL, nullptr, qkvH, qkvL, VtH, VtL,
            NTOK, 3 * ND, ND, ND, ND, 3 * ND,
            0, 0, 0, 0, 0, 0, 1, 1.0f,
            nullptr, nullptr, 3, nullptr, nullptr, nullptr, 0);
        // S = (Q K^T)/8 per (b,h), causal tiles skipped
        gemm_kernel<<<dim3(NT / BN, NT / BM, NB * NH), 256, SMEM_BYTES>>>(
            qkvH, qkvL, qkvH + ND, qkvL + ND, S, nullptr, nullptr, nullptr, nullptr,
            NT, NT, NHD, 3 * ND, 3 * ND, NT,
            (long long)NT * 3 * ND, NHD, (long long)NT * 3 * ND, NHD,
            (long long)NH * NT * NT, (long long)NT * NT, NH, 0.125f,
            nullptr, nullptr, 0, nullptr, nullptr, nullptr, 1);
        softmax_kernel<<<dim3(NT, NB * NH), 128>>>(S, PH, PL);
        // att = P Vt^T per (b,h), K clamped to m0+128 (causal bit1)
        gemm_kernel<<<dim3(1, NT / BM, NB * NH), 256, SMEM_BYTES>>>(
            PH, PL, VtH, VtL, nullptr, attH, attL, nullptr, nullptr,
            NT, NHD, NT, NT, NT, ND,
            (long long)NH * NT * NT, (long long)NT * NT,
            (long long)NH * NHD * NT, (long long)NHD * NT,
            (long long)NT * ND, NHD, NH, 1.0f,
            nullptr, nullptr, 4, nullptr, nullptr, nullptr, 2);
        // x = x + att @ attn_proj^T (fp32)
        gemm_kernel<<<dim3(ND / BN, NTOK / BM, 1), 256, SMEM_BYTES>>>(
            attH, attL, lapH, lapL, x, nullptr, nullptr, nullptr, nullptr,
            NTOK, ND, ND, ND, ND, ND,
            0, 0, 0, 0, 0, 0, 1, 1.0f,
            x, nullptr, 0, nullptr, nullptr, nullptr, 0);

        // ---- MoE ----
        rmsnorm_kernel<<<NTOK, 256>>>(x, ln2, xn, xnH, xnL, 1, 0);
        router_kernel<<<NTOK, 128>>>(xn, rw, probs);
        topk_kernel<<<NE, 1024>>>(probs, sel, wsel);
        // h[e] = gelu( xn[sel[e]] @ fc_w[e]^T ) -> split h (epilogue 1)
        gemm_kernel<<<dim3(NDFF / BN, NTOPK / BM, NE), 256, SMEM_BYTES>>>(
            xnH, xnL, lfwH, lfwL, nullptr, hH, hL, nullptr, nullptr,
            NTOPK, NDFF, ND, ND, ND, NDFF,
            0, 0, (long long)NDFF * ND, 0, (long long)NTOPK * NDFF, 0, 1, 1.0f,
            nullptr, sel, 1, nullptr, nullptr, nullptr, 0);
        // x[sel[e,k]] += w[e,k] * (h[e] @ proj_w[e]^T)   (epilogue 2)
        gemm_kernel<<<dim3(ND / BN, NTOPK / BM, NE), 256, SMEM_BYTES>>>(
            hH, hL, lpjH, lpjL, nullptr, nullptr, nullptr, nullptr, nullptr,
            NTOPK, ND, NDFF, NDFF, NDFF, ND,
            (long long)NTOPK * NDFF, 0, (long long)ND * NDFF, 0, 0, 0, 1, 1.0f,
            nullptr, nullptr, 2, sel, wsel, x, 0);
    }

    rmsnorm_kernel<<<NB, 256>>>(x, lnf_w, xf, nullptr, nullptr, NT, NT - 1);
    lmhead_kernel<<<(NV + 7) / 8, 256>>>(xf, wte, out);
}

// round 13
// speedup vs baseline: 3.2283x; 1.0181x over previous
#include <cuda_runtime.h>
#include <cuda_bf16.h>
#include <math.h>
#include <stdint.h>

#define NB 4
#define NT 1024
#define ND 1024
#define NH 16
#define NL 2
#define NE 8
#define NDFF 4096
#define NV 50257
#define NHD 64
#define NTOK 4096   // NB*NT
#define NTOPK 1024  // CAP*NB*NT/NE

// ---------------- scratch (static device allocations; no cudaMalloc) ----------
__device__ float g_x[NTOK * ND];
__device__ float g_xn[NTOK * ND];           // fp32 xn (router input)
__device__ float g_S[(size_t)NB * NH * NT * NT];
__device__ float g_probs[NTOK * NE];
__device__ float g_wsel[NE * NTOPK];
__device__ int   g_sel[NE * NTOPK];
__device__ float g_xf[NB * ND];

// split bf16 activations
__device__ __nv_bfloat16 g_xnH[NTOK * ND],  g_xnL[NTOK * ND];
__device__ __nv_bfloat16 g_qkvH[NTOK * 3 * ND], g_qkvL[NTOK * 3 * ND];  // V region unused
__device__ __nv_bfloat16 g_VtH[(NB * NH * NHD + 128) * NT], g_VtL[(NB * NH * NHD + 128) * NT];
__device__ __nv_bfloat16 g_PH[(size_t)NB * NH * NT * NT], g_PL[(size_t)NB * NH * NT * NT];
__device__ __nv_bfloat16 g_attH[NTOK * ND], g_attL[NTOK * ND];
__device__ __nv_bfloat16 g_hH[(size_t)NE * NTOPK * NDFF], g_hL[(size_t)NE * NTOPK * NDFF];

// split bf16 weights
__device__ __nv_bfloat16 g_awH[NL * 3 * ND * ND],  g_awL[NL * 3 * ND * ND];
__device__ __nv_bfloat16 g_apwH[NL * ND * ND],     g_apwL[NL * ND * ND];
__device__ __nv_bfloat16 g_fwH[(size_t)NL * NE * NDFF * ND], g_fwL[(size_t)NL * NE * NDFF * ND];
__device__ __nv_bfloat16 g_pjwH[(size_t)NL * NE * ND * NDFF], g_pjwL[(size_t)NL * NE * ND * NDFF];

// ---------------- helpers ------------------------------------------------------
__device__ __forceinline__ void store_split(float v, __nv_bfloat16* ph, __nv_bfloat16* pl) {
    __nv_bfloat16 h = __float2bfloat16(v);
    *ph = h;
    *pl = __float2bfloat16(v - __bfloat162float(h));
}

__device__ __forceinline__ void split2(float x, float y, uint32_t& h, uint32_t& l) {
    __nv_bfloat16 hx = __float2bfloat16(x), hy = __float2bfloat16(y);
    __nv_bfloat16 lx = __float2bfloat16(x - __bfloat162float(hx));
    __nv_bfloat16 ly = __float2bfloat16(y - __bfloat162float(hy));
    uint16_t uhx = *(uint16_t*)&hx, uhy = *(uint16_t*)&hy;
    uint16_t ulx = *(uint16_t*)&lx, uly = *(uint16_t*)&ly;
    h = ((uint32_t)uhy << 16) | uhx;
    l = ((uint32_t)uly << 16) | ulx;
}

// split a float4 -> packed hi uint2 / lo uint2
__device__ __forceinline__ void split4(float4 v, uint2& h, uint2& l) {
    uint32_t h0, l0, h1, l1;
    split2(v.x, v.y, h0, l0);
    split2(v.z, v.w, h1, l1);
    h = make_uint2(h0, h1);
    l = make_uint2(l0, l1);
}

__device__ __forceinline__ uint32_t smem_u32(const void* p) {
    return (uint32_t)__cvta_generic_to_shared(p);
}

__device__ __forceinline__ void cp16(void* dst_smem, const void* src) {
    asm volatile("cp.async.cg.shared.global [%0], [%1], 16;"
                 :: "r"(smem_u32(dst_smem)), "l"(src));
}
#define CP_COMMIT() asm volatile("cp.async.commit_group;")
#define CP_WAIT0()  asm volatile("cp.async.wait_group 0;")

__device__ __forceinline__ void mma_bf16(float* c, const uint32_t* a,
                                         uint32_t b0, uint32_t b1) {
    asm volatile(
        "mma.sync.aligned.m16n8k16.row.col.f32.bf16.bf16.f32 "
        "{%0,%1,%2,%3}, {%4,%5,%6,%7}, {%8,%9}, {%0,%1,%2,%3};"
        : "+f"(c[0]), "+f"(c[1]), "+f"(c[2]), "+f"(c[3])
        : "r"(a[0]), "r"(a[1]), "r"(a[2]), "r"(a[3]), "r"(b0), "r"(b1));
}

__device__ __forceinline__ void ldsm_x4(uint32_t* r, uint32_t addr) {
    asm volatile("ldmatrix.sync.aligned.m8n8.x4.shared.b16 {%0,%1,%2,%3}, [%4];"
                 : "=r"(r[0]), "=r"(r[1]), "=r"(r[2]), "=r"(r[3]) : "r"(addr));
}

// ---------------- fp32 -> (hi, lo) bf16 conversion (packed stores) ------------
__global__ void split_kernel(const float4* __restrict__ src, uint2* __restrict__ h2,
                             uint2* __restrict__ l2, int n4) {
    int i = blockIdx.x * blockDim.x + threadIdx.x;
    if (i < n4) {
        uint2 h, l;
        split4(src[i], h, l);
        h2[i] = h;
        l2[i] = l;
    }
}

// ---------------- embedding (vectorized) ---------------------------------------
__global__ void embed_kernel(const int* __restrict__ idx, const float* __restrict__ wte,
                             const float* __restrict__ wpe, float* __restrict__ x) {
    int n = blockIdx.x;
    int t = n & (NT - 1);
    long long r = idx[n];
    const float4* a = (const float4*)(wte + r * ND);
    const float4* b = (const float4*)(wpe + (long long)t * ND);
    float4* o = (float4*)(x + (long long)n * ND);
    int d = threadIdx.x;                  // 256 threads, ND/4 = 256 float4
    float4 va = a[d], vb = b[d];
    o[d] = make_float4(va.x + vb.x, va.y + vb.y, va.z + vb.z, va.w + vb.w);
}

// ---------------- rmsnorm (vectorized; fp32 and/or split-bf16 output) ---------
__global__ void rmsnorm_kernel(const float* __restrict__ x, const float* __restrict__ w,
                               float* __restrict__ outF,
                               __nv_bfloat16* __restrict__ outH,
                               __nv_bfloat16* __restrict__ outL,
                               int rowMul, int rowAdd) {
    int orow = blockIdx.x;
    long long irow = (long long)orow * rowMul + rowAdd;
    const float4* xr = (const float4*)(x + irow * ND);
    const float4* w4 = (const float4*)w;
    __shared__ float red[256];
    int tid = threadIdx.x;                // 256 threads, 1 float4 each
    float4 v = xr[tid];
    float s = v.x * v.x + v.y * v.y + v.z * v.z + v.w * v.w;
    red[tid] = s; __syncthreads();
    for (int o = 128; o > 0; o >>= 1) {
        if (tid < o) red[tid] += red[tid + o];
        __syncthreads();
    }
    float scale = 1.0f / sqrtf(red[0] * (1.0f / ND) + 1e-6f);
    float4 wv = w4[tid];
    float4 r4 = make_float4(v.x * scale * wv.x, v.y * scale * wv.y,
                            v.z * scale * wv.z, v.w * scale * wv.w);
    long long ob4 = (long long)orow * (ND / 4) + tid;
    if (outF) ((float4*)outF)[ob4] = r4;
    if (outH) {
        uint2 h, l;
        split4(r4, h, l);
        ((uint2*)outH)[ob4] = h;
        ((uint2*)outL)[ob4] = l;
    }
}

// ---------------- tensor-core batched GEMM (pre-split bf16 operands) ----------
// C = alpha * A @ B^T with A=[M,K] via (AH,AL), B=[N,K] via (BH,BL), both row-major.
// 3-term split product: Ah*Bh + Ah*Bl + Al*Bh. cp.async double-buffered.
// epilogue: 0 fp32 store (+residual), 1 GELU->split, 2 scaled atomic scatter,
//           3 qkv special (Q,K split store; V -> transposed Vt split store),
//           4 plain split store.
// causal: bit0 -> skip tiles with n0 > m0+BM-1 (score GEMM)
//         bit1 -> clamp K to m0+BM (PV GEMM)
#define BM 128
#define BN 128
#define BK 32
#define LDS_PAD 40
#define MT (BM * LDS_PAD)
#define ST (4 * MT)
#define SMEM_BYTES (2 * ST * 2)

__global__ __launch_bounds__(256, 2) void gemm_kernel(
    const __nv_bfloat16* __restrict__ AH, const __nv_bfloat16* __restrict__ AL,
    const __nv_bfloat16* __restrict__ BH, const __nv_bfloat16* __restrict__ BL,
    float* __restrict__ C, __nv_bfloat16* __restrict__ CH, __nv_bfloat16* __restrict__ CL,
    __nv_bfloat16* __restrict__ VtH, __nv_bfloat16* __restrict__ VtL,
    int M, int N, int K, int lda, int ldb, int ldc,
    long long sA1, long long sA2, long long sB1, long long sB2,
    long long sC1, long long sC2, int zdiv, float alpha,
    const float* __restrict__ residual, const int* __restrict__ rowsA,
    int epilogue, const int* __restrict__ rowsOut,
    const float* __restrict__ rowScale, float* __restrict__ scatter, int causal)
{
    extern __shared__ __nv_bfloat16 sm[];

    int m0 = blockIdx.y * BM, n0 = blockIdx.x * BN;
    if ((causal & 1) && n0 > m0 + BM - 1) return;   // fully-masked score tile

    int z = blockIdx.z;
    int z1 = z / zdiv, z2 = z - z1 * zdiv;
    long long offA = z1 * sA1 + z2 * sA2;
    long long offB = z1 * sB1 + z2 * sB2;
    long long offC = z1 * sC1 + z2 * sC2;
    AH += offA; AL += offA;
    BH += offB; BL += offB;
    if (C)  C  += offC;
    if (CH) { CH += offC; CL += offC; }

    int tid = threadIdx.x;
    int lane = tid & 31;
    int warpId = tid >> 5;
    int wm = (warpId & 3) * 32;
    int wn = (warpId >> 2) * 64;

    float acc[2][8][4];
#pragma unroll
    for (int mi = 0; mi < 2; mi++)
#pragma unroll
        for (int ni = 0; ni < 8; ni++)
#pragma unroll
            for (int t = 0; t < 4; t++) acc[mi][ni][t] = 0.f;

    int am = tid >> 1, ac = (tid & 1) * 16;
    long long arow = m0 + am;
    if (rowsA) arow = rowsA[(long long)z * M + m0 + am];
    const __nv_bfloat16* gAH = AH + arow * (long long)lda + ac;
    const __nv_bfloat16* gAL = AL + arow * (long long)lda + ac;
    const __nv_bfloat16* gBH = BH + (long long)(n0 + am) * ldb + ac;
    const __nv_bfloat16* gBL = BL + (long long)(n0 + am) * ldb + ac;
    int dstA = am * LDS_PAD + ac;

    int Klim = (causal & 2) ? (m0 + BM < K ? m0 + BM : K) : K;
    int nTiles = Klim / BK;

    {
        __nv_bfloat16* s = sm;
        cp16(s + dstA,               gAH);
        cp16(s + dstA + 8,           gAH + 8);
        cp16(s + MT + dstA,          gAL);
        cp16(s + MT + dstA + 8,      gAL + 8);
        cp16(s + 2 * MT + dstA,      gBH);
        cp16(s + 2 * MT + dstA + 8,  gBH + 8);
        cp16(s + 3 * MT + dstA,      gBL);
        cp16(s + 3 * MT + dstA + 8,  gBL + 8);
        CP_COMMIT();
    }

    int arl = lane & 15;
    int acl = (lane >> 4) * 8;
    int brl = (lane & 7) + ((lane & 16) >> 1);

    for (int it = 0; it < nTiles; it++) {
        CP_WAIT0();
        __syncthreads();

        if (it + 1 < nTiles) {
            int k0 = (it + 1) * BK;
            __nv_bfloat16* s = sm + ((it + 1) & 1) * ST;
            cp16(s + dstA,               gAH + k0);
            cp16(s + dstA + 8,           gAH + k0 + 8);
            cp16(s + MT + dstA,          gAL + k0);
            cp16(s + MT + dstA + 8,      gAL + k0 + 8);
            cp16(s + 2 * MT + dstA,      gBH + k0);
            cp16(s + 2 * MT + dstA + 8,  gBH + k0 + 8);
            cp16(s + 3 * MT + dstA,      gBL + k0);
            cp16(s + 3 * MT + dstA + 8,  gBL + k0 + 8);
            CP_COMMIT();
        }

        const __nv_bfloat16* pAH = sm + (it & 1) * ST;
        const __nv_bfloat16* pAL = pAH + MT;
        const __nv_bfloat16* pBH = pAH + 2 * MT;
        const __nv_bfloat16* pBL = pAH + 3 * MT;

#pragma unroll
        for (int ks = 0; ks < 2; ks++) {
            int kk = ks * 16;
            uint32_t ah[2][4], al[2][4];
#pragma unroll
            for (int mi = 0; mi < 2; mi++) {
                int r0 = wm + mi * 16 + arl;
                ldsm_x4(ah[mi], smem_u32(pAH + r0 * LDS_PAD + kk + acl));
                ldsm_x4(al[mi], smem_u32(pAL + r0 * LDS_PAD + kk + acl));
            }
            int bcl = kk + (lane & 8);
#pragma unroll
            for (int nip = 0; nip < 4; nip++) {
                int cn = wn + nip * 16 + brl;
                uint32_t bh[4], bl[4];
                ldsm_x4(bh, smem_u32(pBH + cn * LDS_PAD + bcl));
                ldsm_x4(bl, smem_u32(pBL + cn * LDS_PAD + bcl));
#pragma unroll
                for (int mi = 0; mi < 2; mi++) {
                    mma_bf16(acc[mi][2 * nip], ah[mi], bh[0], bh[1]);
                    mma_bf16(acc[mi][2 * nip], ah[mi], bl[0], bl[1]);
                    mma_bf16(acc[mi][2 * nip], al[mi], bh[0], bh[1]);
                    mma_bf16(acc[mi][2 * nip + 1], ah[mi], bh[2], bh[3]);
                    mma_bf16(acc[mi][2 * nip + 1], ah[mi], bl[2], bl[3]);
                    mma_bf16(acc[mi][2 * nip + 1], al[mi], bh[2], bh[3]);
                }
            }
        }
        __syncthreads();
    }

    int fr = lane >> 2;
    int fc = (lane & 3) * 2;
#pragma unroll
    for (int mi = 0; mi < 2; mi++) {
#pragma unroll
        for (int ni = 0; ni < 8; ni++) {
            int mBase = m0 + wm + mi * 16 + fr;
            int nBase = n0 + wn + ni * 8 + fc;
#pragma unroll
            for (int half = 0; half < 2; half++) {
                int m = mBase + half * 8;
                if (m >= M) continue;
#pragma unroll
                for (int t = 0; t < 2; t++) {
                    int n = nBase + t;
                    if (n >= N) continue;
                    float v = acc[mi][ni][half * 2 + t] * alpha;
                    long long ci = (long long)m * ldc + n;
                    if (epilogue == 0) {
                        if (residual) v += residual[ci];
                        C[ci] = v;
                    } else if (epilogue == 1) {
                        v = 0.5f * v * (1.0f + erff(v * 0.70710678118654752440f));
                        store_split(v, CH + ci, CL + ci);
                    } else if (epilogue == 2) {
                        long long rr = rowsOut[(long long)z * M + m];
                        atomicAdd(&scatter[rr * ldc + n],
                                  rowScale[(long long)z * M + m] * v);
                    } else if (epilogue == 3) {
                        if (n < 2 * ND) {
                            store_split(v, CH + ci, CL + ci);
                        } else {
                            int b = m >> 10, tt = m & (NT - 1);
                            int c = n - 2 * ND;
                            int h = c >> 6, d = c & (NHD - 1);
                            long long vi = ((long long)((b * NH + h) * NHD + d)) * NT + tt;
                            store_split(v, VtH + vi, VtL + vi);
                        }
                    } else {
                        store_split(v, CH + ci, CL + ci);
                    }
                }
            }
        }
    }
}

// ---------------- causal softmax (vectorized): fp32 S row -> split-bf16 P -----
__global__ void softmax_kernel(float* __restrict__ S, __nv_bfloat16* __restrict__ PH,
                               __nv_bfloat16* __restrict__ PL) {
    int q = blockIdx.x;
    long long z = blockIdx.y;
    long long base = z * (long long)NT * NT + (long long)q * NT;
    float4* row4 = (float4*)(S + base);
    int len = q + 1;
    int lenv = (len + 3) >> 2;            // float4 slots containing valid data
    int nv = (((q >> 7) + 1) << 7) >> 2;  // slots to emit in P (next 128 boundary)
    __shared__ float red[128];
    int tid = threadIdx.x;

    // pass 1: max over valid
    float mx = -1e30f;
    for (int v = tid; v < lenv; v += 128) {
        float4 f = row4[v];
        int i0 = v * 4;
        if (i0 + 0 < len) mx = fmaxf(mx, f.x);
        if (i0 + 1 < len) mx = fmaxf(mx, f.y);
        if (i0 + 2 < len) mx = fmaxf(mx, f.z);
        if (i0 + 3 < len) mx = fmaxf(mx, f.w);
    }
    red[tid] = mx; __syncthreads();
    for (int o = 64; o > 0; o >>= 1) {
        if (tid < o) red[tid] = fmaxf(red[tid], red[tid + o]);
        __syncthreads();
    }
    mx = red[0]; __syncthreads();

    // pass 2: exp (invalid lanes -> 0), accumulate sum, store back
    float s = 0.f;
    for (int v = tid; v < lenv; v += 128) {
        float4 f = row4[v];
        int i0 = v * 4;
        f.x = (i0 + 0 < len) ? expf(f.x - mx) : 0.f;
        f.y = (i0 + 1 < len) ? expf(f.y - mx) : 0.f;
        f.z = (i0 + 2 < len) ? expf(f.z - mx) : 0.f;
        f.w = (i0 + 3 < len) ? expf(f.w - mx) : 0.f;
        s += f.x + f.y + f.z + f.w;
        row4[v] = f;
    }
    red[tid] = s; __syncthreads();
    for (int o = 64; o > 0; o >>= 1) {
        if (tid < o) red[tid] += red[tid + o];
        __syncthreads();
    }
    float inv = 1.0f / red[0];

    // pass 3: normalized split-bf16 store, zero-fill to the 128 boundary
    uint2* PH2 = (uint2*)(PH + base);
    uint2* PL2 = (uint2*)(PL + base);
    for (int v = tid; v < nv; v += 128) {
        uint2 h = make_uint2(0u, 0u), l = make_uint2(0u, 0u);
        if (v < lenv) {
            float4 f = row4[v];
            f.x *= inv; f.y *= inv; f.z *= inv; f.w *= inv;
            split4(f, h, l);
        }
        PH2[v] = h;
        PL2[v] = l;
    }
}

// ---------------- router logits + softmax over experts -----------------------
__global__ void router_kernel(const float* __restrict__ xn, const float* __restrict__ wr,
                              float* __restrict__ probs) {
    int n = blockIdx.x;
    const float* xr = xn + (long long)n * ND;
    float acc[NE];
#pragma unroll
    for (int e = 0; e < NE; e++) acc[e] = 0.f;
    for (int d = threadIdx.x; d < ND; d += 128) {
        float xv = xr[d];
#pragma unroll
        for (int e = 0; e < NE; e++) acc[e] += xv * wr[e * ND + d];
    }
    __shared__ float red[128];
    __shared__ float logit[NE];
    for (int e = 0; e < NE; e++) {
        red[threadIdx.x] = acc[e]; __syncthreads();
        for (int o = 64; o > 0; o >>= 1) {
            if (threadIdx.x < o) red[threadIdx.x] += red[threadIdx.x + o];
            __syncthreads();
        }
        if (threadIdx.x == 0) logit[e] = red[0];
        __syncthreads();
    }
    if (threadIdx.x == 0) {
        float mx = logit[0];
        for (int e = 1; e < NE; e++) mx = fmaxf(mx, logit[e]);
        float s = 0.f; float ex[NE];
        for (int e = 0; e < NE; e++) { ex[e] = expf(logit[e] - mx); s += ex[e]; }
        float inv = 1.0f / s;
        for (int e = 0; e < NE; e++) probs[(long long)n * NE + e] = ex[e] * inv;
    }
}

// ---------------- per-expert top-k via in-smem bitonic sort -------------------
__global__ void topk_kernel(const float* __restrict__ probs, int* __restrict__ sel,
                            float* __restrict__ weights) {
    int e = blockIdx.x;
    __shared__ float v[NTOK];
    __shared__ int ix[NTOK];
    int tid = threadIdx.x;
    for (int i = tid; i < NTOK; i += 1024) { v[i] = probs[(long long)i * NE + e]; ix[i] = i; }
    __syncthreads();
    for (int k = 2; k <= NTOK; k <<= 1) {
        for (int j = k >> 1; j > 0; j >>= 1) {
            for (int i = tid; i < NTOK; i += 1024) {
                int p = i ^ j;
                if (p > i) {
                    float va = v[i], vb = v[p];
                    int ia = ix[i], ib = ix[p];
                    bool sw;
                    if ((i & k) == 0) sw = (vb > va) || (vb == va && ib < ia);
                    else              sw = (va > vb) || (va == vb && ia < ib);
                    if (sw) { v[i] = vb; v[p] = va; ix[i] = ib; ix[p] = ia; }
                }
            }
            __syncthreads();
        }
    }
    for (int i = tid; i < NTOPK; i += 1024) {
        sel[e * NTOPK + i] = ix[i];
        weights[e * NTOPK + i] = v[i];
    }
}

// ---------------- LM head (vectorized): last-token logits ---------------------
__global__ void lmhead_kernel(const float* __restrict__ xf, const float* __restrict__ wte,
                              float* __restrict__ out) {
    __shared__ float xs[NB * ND];
    for (int i = threadIdx.x; i < NB * ND / 4; i += 256)
        ((float4*)xs)[i] = ((const float4*)xf)[i];
    __syncthreads();
    int warp = threadIdx.x >> 5, lane = threadIdx.x & 31;
    int vtok = blockIdx.x * 8 + warp;
    if (vtok < NV) {
        const float4* wrow = (const float4*)(wte + (long long)vtok * ND);
        float a0 = 0.f, a1 = 0.f, a2 = 0.f, a3 = 0.f;
#pragma unroll
        for (int it = 0; it < 8; it++) {
            int d4 = it * 32 + lane;            // float4 index
            float4 w = wrow[d4];
            const float* x0 = xs + d4 * 4;
            a0 += w.x * x0[0] + w.y * x0[1] + w.z * x0[2] + w.w * x0[3];
            const float* x1 = xs + ND + d4 * 4;
            a1 += w.x * x1[0] + w.y * x1[1] + w.z * x1[2] + w.w * x1[3];
            const float* x2 = xs + 2 * ND + d4 * 4;
            a2 += w.x * x2[0] + w.y * x2[1] + w.z * x2[2] + w.w * x2[3];
            const float* x3 = xs + 3 * ND + d4 * 4;
            a3 += w.x * x3[0] + w.y * x3[1] + w.z * x3[2] + w.w * x3[3];
        }
#pragma unroll
        for (int o = 16; o > 0; o >>= 1) {
            a0 += __shfl_down_sync(0xffffffffu, a0, o);
            a1 += __shfl_down_sync(0xffffffffu, a1, o);
            a2 += __shfl_down_sync(0xffffffffu, a2, o);
            a3 += __shfl_down_sync(0xffffffffu, a3, o);
        }
        if (lane == 0) {
            out[0 * NV + vtok] = a0;
            out[1 * NV + vtok] = a1;
            out[2 * NV + vtok] = a2;
            out[3 * NV + vtok] = a3;
        }
    }
}

// ---------------- host-side orchestration ------------------------------------
extern "C" void kernel_launch(void* const* d_in, const int* in_sizes, int n_in,
                              void* d_out, int out_size) {
    (void)in_sizes; (void)n_in; (void)out_size;
    const int*   idx         = (const int*)d_in[0];
    const float* wte         = (const float*)d_in[1];
    const float* wpe         = (const float*)d_in[2];
    const float* ln1_w       = (const float*)d_in[3];
    const float* attn_w      = (const float*)d_in[4];
    const float* attn_proj_w = (const float*)d_in[5];
    const float* ln2_w       = (const float*)d_in[6];
    const float* router_w    = (const float*)d_in[7];
    const float* fc_w        = (const float*)d_in[8];
    const float* proj_w      = (const float*)d_in[9];
    const float* lnf_w       = (const float*)d_in[10];
    float* out = (float*)d_out;

    void* p;
#define GET(sym, T, name) cudaGetSymbolAddress(&p, sym); T* name = (T*)p
    GET(g_x, float, x);
    GET(g_xn, float, xn);
    GET(g_S, float, S);
    GET(g_probs, float, probs);
    GET(g_wsel, float, wsel);
    GET(g_sel, int, sel);
    GET(g_xf, float, xf);
    GET(g_xnH, __nv_bfloat16, xnH);   GET(g_xnL, __nv_bfloat16, xnL);
    GET(g_qkvH, __nv_bfloat16, qkvH); GET(g_qkvL, __nv_bfloat16, qkvL);
    GET(g_VtH, __nv_bfloat16, VtH);   GET(g_VtL, __nv_bfloat16, VtL);
    GET(g_PH, __nv_bfloat16, PH);     GET(g_PL, __nv_bfloat16, PL);
    GET(g_attH, __nv_bfloat16, attH); GET(g_attL, __nv_bfloat16, attL);
    GET(g_hH, __nv_bfloat16, hH);     GET(g_hL, __nv_bfloat16, hL);
    GET(g_awH, __nv_bfloat16, awH);   GET(g_awL, __nv_bfloat16, awL);
    GET(g_apwH, __nv_bfloat16, apwH); GET(g_apwL, __nv_bfloat16, apwL);
    GET(g_fwH, __nv_bfloat16, fwH);   GET(g_fwL, __nv_bfloat16, fwL);
    GET(g_pjwH, __nv_bfloat16, pjwH); GET(g_pjwL, __nv_bfloat16, pjwL);
#undef GET

    cudaFuncSetAttribute(gemm_kernel, cudaFuncAttributeMaxDynamicSharedMemorySize, SMEM_BYTES);

    {
        int n;
        n = NL * 3 * ND * ND;
        split_kernel<<<(n / 4 + 255) / 256, 256>>>((const float4*)attn_w, (uint2*)awH, (uint2*)awL, n / 4);
        n = NL * ND * ND;
        split_kernel<<<(n / 4 + 255) / 256, 256>>>((const float4*)attn_proj_w, (uint2*)apwH, (uint2*)apwL, n / 4);
        n = NL * NE * NDFF * ND;
        split_kernel<<<(n / 4 + 255) / 256, 256>>>((const float4*)fc_w, (uint2*)fwH, (uint2*)fwL, n / 4);
        split_kernel<<<(n / 4 + 255) / 256, 256>>>((const float4*)proj_w, (uint2*)pjwH, (uint2*)pjwL, n / 4);
    }

    embed_kernel<<<NTOK, 256>>>(idx, wte, wpe, x);

    for (int l = 0; l < NL; l++) {
        const float* ln1 = ln1_w + l * ND;
        const float* ln2 = ln2_w + l * ND;
        const float* rw  = router_w + (long long)l * NE * ND;
        __nv_bfloat16* lawH = awH + (long long)l * 3 * ND * ND;
        __nv_bfloat16* lawL = awL + (long long)l * 3 * ND * ND;
        __nv_bfloat16* lapH = apwH + (long long)l * ND * ND;
        __nv_bfloat16* lapL = apwL + (long long)l * ND * ND;
        __nv_bfloat16* lfwH = fwH + (long long)l * NE * NDFF * ND;
        __nv_bfloat16* lfwL = fwL + (long long)l * NE * NDFF * ND;
        __nv_bfloat16* lpjH = pjwH + (long long)l * NE * ND * NDFF;
        __nv_bfloat16* lpjL = pjwL + (long long)l * NE * ND * NDFF;

        // ---- attention ----
        rmsnorm_kernel<<<NTOK, 256>>>(x, ln1, nullptr, xnH, xnL, 1, 0);
        // qkv (epilogue 3: Q,K -> split qkv; V -> transposed Vt)
        gemm_kernel<<<dim3(3 * ND / BN, NTOK / BM, 1), 256, SMEM_BYTES>>>(
            xnH, xnL, lawH, lawL, nullptr, qkvH, qkvL, VtH, VtL,
            NTOK, 3 * ND, ND, ND, ND, 3 * ND,
            0, 0, 0, 0, 0, 0, 1, 1.0f,
            nullptr, nullptr, 3, nullptr, nullptr, nullptr, 0);
        // S = (Q K^T)/8 per (b,h), causal tiles skipped
        gemm_kernel<<<dim3(NT / BN, NT / BM, NB * NH), 256, SMEM_BYTES>>>(
            qkvH, qkvL, qkvH + ND, qkvL + ND, S, nullptr, nullptr, nullptr, nullptr,
            NT, NT, NHD, 3 * ND, 3 * ND, NT,
            (long long)NT * 3 * ND, NHD, (long long)NT * 3 * ND, NHD,
            (long long)NH * NT * NT, (long long)NT * NT, NH, 0.125f,
            nullptr, nullptr, 0, nullptr, nullptr, nullptr, 1);
        softmax_kernel<<<dim3(NT, NB * NH), 128>>>(S, PH, PL);
        // att = P Vt^T per (b,h), K clamped to m0+128 (causal bit1)
        gemm_kernel<<<dim3(1, NT / BM, NB * NH), 256, SMEM_BYTES>>>(
            PH, PL, VtH, VtL, nullptr, attH, attL, nullptr, nullptr,
            NT, NHD, NT, NT, NT, ND,
            (long long)NH * NT * NT, (long long)NT * NT,
            (long long)NH * NHD * NT, (long long)NHD * NT,
            (long long)NT * ND, NHD, NH, 1.0f,
            nullptr, nullptr, 4, nullptr, nullptr, nullptr, 2);
        // x = x + att @ attn_proj^T (fp32)
        gemm_kernel<<<dim3(ND / BN, NTOK / BM, 1), 256, SMEM_BYTES>>>(
            attH, attL, lapH, lapL, x, nullptr, nullptr, nullptr, nullptr,
            NTOK, ND, ND, ND, ND, ND,
            0, 0, 0, 0, 0, 0, 1, 1.0f,
            x, nullptr, 0, nullptr, nullptr, nullptr, 0);

        // ---- MoE ----
        rmsnorm_kernel<<<NTOK, 256>>>(x, ln2, xn, xnH, xnL, 1, 0);
        router_kernel<<<NTOK, 128>>>(xn, rw, probs);
        topk_kernel<<<NE, 1024>>>(probs, sel, wsel);
        // h[e] = gelu( xn[sel[e]] @ fc_w[e]^T ) -> split h (epilogue 1)
        gemm_kernel<<<dim3(NDFF / BN, NTOPK / BM, NE), 256, SMEM_BYTES>>>(
            xnH, xnL, lfwH, lfwL, nullptr, hH, hL, nullptr, nullptr,
            NTOPK, NDFF, ND, ND, ND, NDFF,
            0, 0, (long long)NDFF * ND, 0, (long long)NTOPK * NDFF, 0, 1, 1.0f,
            nullptr, sel, 1, nullptr, nullptr, nullptr, 0);
        // x[sel[e,k]] += w[e,k] * (h[e] @ proj_w[e]^T)   (epilogue 2)
        gemm_kernel<<<dim3(ND / BN, NTOPK / BM, NE), 256, SMEM_BYTES>>>(
            hH, hL, lpjH, lpjL, nullptr, nullptr, nullptr, nullptr, nullptr,
            NTOPK, ND, NDFF, NDFF, NDFF, ND,
            (long long)NTOPK * NDFF, 0, (long long)ND * NDFF, 0, 0, 0, 1, 1.0f,
            nullptr, nullptr, 2, sel, wsel, x, 0);
    }

    rmsnorm_kernel<<<NB, 256>>>(x, lnf_w, xf, nullptr, nullptr, NT, NT - 1);
    lmhead_kernel<<<(NV + 7) / 8, 256>>>(xf, wte, out);
}